// round 8
// baseline (speedup 1.0000x reference)
#include <cuda_runtime.h>
#include <cuda_fp16.h>
#include <stdint.h>

#define NTOK    294912
#define BM      64
#define NBLK    (NTOK / BM)      // 4608
#define THREADS 256

// ---- smem byte offsets ----
#define OFF_A_HI 0               // 64 x 264 fp16 (row stride 528B)
#define OFF_A_LO 33792
#define OFF_B    67584           // 4 pairs x 3 stages x 3072B
#define PAIR_RING 9216
#define BSTG     3072
#define OFF_STAGE OFF_B          // aliases B: 64 x 76 f32 (19456B)
#define OFF_QW1  (OFF_B + 20480) // 64*20 f32
#define OFF_P1   (OFF_B + 26624) // 256 f32 partials (cls)
#define OFF_P2   (OFF_B + 27648) // 256 f32 partials (quality)
#define OFF_BIAS 104448          // 256 f32
#define OFF_STAT 105472          // 64*20 f32
#define SMEM_BYTES 110592

#define A_STRIDE 528
#define B_STRIDE 48

// fp16 weights, written by prep kernel each launch
__device__ __half g_wh[4][65536];    // 0=rw1 1=rw2 2=cw1 3=cw2
__device__ __half g_w3h[96 * 256];   // rw3 padded to 96 rows

// ---------------- helpers ----------------
__device__ __forceinline__ uint32_t smem_u32(const void* p) {
    uint32_t a;
    asm("{ .reg .u64 t; cvta.to.shared.u64 t, %1; cvt.u32.u64 %0, t; }"
        : "=r"(a) : "l"(p));
    return a;
}
__device__ __forceinline__ void ldsm4(uint32_t* r, uint32_t addr) {
    asm volatile("ldmatrix.sync.aligned.m8n8.x4.shared.b16 {%0,%1,%2,%3}, [%4];"
        : "=r"(r[0]), "=r"(r[1]), "=r"(r[2]), "=r"(r[3]) : "r"(addr));
}
__device__ __forceinline__ void mmaf16(float* c, const uint32_t* a, const uint32_t* b) {
    asm volatile("mma.sync.aligned.m16n8k16.row.col.f32.f16.f16.f32 "
        "{%0,%1,%2,%3}, {%4,%5,%6,%7}, {%8,%9}, {%0,%1,%2,%3};"
        : "+f"(c[0]), "+f"(c[1]), "+f"(c[2]), "+f"(c[3])
        : "r"(a[0]), "r"(a[1]), "r"(a[2]), "r"(a[3]), "r"(b[0]), "r"(b[1]));
}
__device__ __forceinline__ void cp16(uint32_t dst, const void* src) {
    asm volatile("cp.async.cg.shared.global [%0], [%1], 16;" :: "r"(dst), "l"(src));
}
#define CP_COMMIT() asm volatile("cp.async.commit_group;" ::: "memory")
#define CP_WAIT1()  asm volatile("cp.async.wait_group 1;" ::: "memory")
__device__ __forceinline__ void bar_pair(int id) {
    asm volatile("bar.sync %0, 64;" :: "r"(id) : "memory");
}

// exact fp16 hi/lo split of an fp32 value
__device__ __forceinline__ void split2h(float v, unsigned short& h, unsigned short& l) {
    __half hh = __float2half_rn(v);
    float fh = __half2float(hh);
    __half hl = __float2half_rn(v - fh);
    h = *(unsigned short*)&hh;
    l = *(unsigned short*)&hl;
}
__device__ __forceinline__ float h2f(unsigned short us) {
    __half_raw r; r.x = us;
    return __half2float(*(__half*)&r);
}
__device__ __forceinline__ float sigmoidf_(float v) { return 1.0f / (1.0f + __expf(-v)); }

// ---------------- prep kernel: weights -> fp16 ----------------
__global__ void prep_kernel(const float* rw1, const float* rw2,
                            const float* cw1, const float* cw2,
                            const float* rw3) {
    int i = blockIdx.x * 256 + threadIdx.x;
    if (i < 65536) {
        g_wh[0][i] = __float2half_rn(rw1[i]);
        g_wh[1][i] = __float2half_rn(rw2[i]);
        g_wh[2][i] = __float2half_rn(cw1[i]);
        g_wh[3][i] = __float2half_rn(cw2[i]);
        if (i < 96 * 256) {
            int row = i >> 8;
            g_w3h[i] = __float2half_rn((row < 68) ? rw3[i] : 0.0f);
        }
    }
}

// ---------------- device subroutines ----------------
__device__ __forceinline__ void load_x_split(char* sm, const float* xg, int tid) {
    for (int idx = tid; idx < 4096; idx += THREADS) {
        int row = idx >> 6;
        int c4  = (idx & 63) << 2;
        float4 v = *(const float4*)(xg + row * 256 + c4);
        unsigned short h0,h1,h2,h3,l0,l1,l2,l3;
        split2h(v.x,h0,l0); split2h(v.y,h1,l1); split2h(v.z,h2,l2); split2h(v.w,h3,l3);
        uint2 uh, ul;
        uh.x = (uint32_t)h0 | ((uint32_t)h1 << 16);
        uh.y = (uint32_t)h2 | ((uint32_t)h3 << 16);
        ul.x = (uint32_t)l0 | ((uint32_t)l1 << 16);
        ul.y = (uint32_t)l2 | ((uint32_t)l3 << 16);
        *(uint2*)(sm + OFF_A_HI + row * A_STRIDE + c4 * 2) = uh;
        *(uint2*)(sm + OFF_A_LO + row * A_STRIDE + c4 * 2) = ul;
    }
}

// issue first 2 B slices of a 256-row layer (hoistable across serial regions)
__device__ __forceinline__ void prologue256(uint32_t smb, const __half* __restrict__ w, int tid) {
    const int lane = tid & 31, wid = tid >> 5;
    const int wm = wid >> 2, wn = wid & 3;
    const uint32_t pairbase = smb + OFF_B + (uint32_t)(wn * PAIR_RING);
    const uint32_t bdst = pairbase + (uint32_t)((wm*32 + lane) * B_STRIDE);
    const __half* src = w + (wn*64 + wm*32 + lane) * 256;
    cp16(bdst, src);               cp16(bdst + 16, src + 8);               CP_COMMIT();
    cp16(bdst + BSTG, src + 16);   cp16(bdst + BSTG + 16, src + 24);       CP_COMMIT();
}

// 64x256x256 layer mainloop. Per-pair private 3-stage ring; pair-local barriers.
// REQUIRES prologue256(w) already issued with matching commit cadence.
__device__ __forceinline__ void gemm256(char* sm, uint32_t smb,
    const __half* __restrict__ w, float acc[2][8][4], int tid)
{
    const int lane = tid & 31, wid = tid >> 5;
    const int wm = wid >> 2, wn = wid & 3;
    const int a_row  = (lane & 7) + ((lane >> 3) & 1) * 8;
    const int a_koff = (lane >> 4) * 8;
    const int b_n    = (lane & 7) + ((lane >> 4) << 3);
    const int b_koff = ((lane >> 3) & 1) * 8;
    const int barid  = 1 + wn;

    const uint32_t aHi = smb + OFF_A_HI + (uint32_t)((wm*32 + a_row) * A_STRIDE + a_koff * 2);
    const uint32_t aLo = aHi + (OFF_A_LO - OFF_A_HI);
    const uint32_t pairbase = smb + OFF_B + (uint32_t)(wn * PAIR_RING);
    const uint32_t bOff = (uint32_t)(b_n * B_STRIDE + b_koff * 2);

    const uint32_t bdst = pairbase + (uint32_t)((wm*32 + lane) * B_STRIDE);
    const __half* src = w + (wn*64 + wm*32 + lane) * 256;

    int st_rd = 0, st_wr = 2;
    for (int ks = 0; ks < 16; ks++) {
        CP_WAIT1();
        bar_pair(barid);
        if (ks + 2 < 16) {
            uint32_t d2 = bdst + (uint32_t)(st_wr * BSTG);
            const __half* s2 = src + (ks + 2) * 16;
            cp16(d2, s2);
            cp16(d2 + 16, s2 + 8);
        }
        CP_COMMIT();

        const uint32_t bb = pairbase + (uint32_t)(st_rd * BSTG) + bOff;
        st_rd = (st_rd == 2) ? 0 : st_rd + 1;
        st_wr = (st_wr == 2) ? 0 : st_wr + 1;

        uint32_t bh[8][2];
#pragma unroll
        for (int p = 0; p < 4; p++) {
            uint32_t r[4];
            ldsm4(r, bb + p * (16 * B_STRIDE));
            bh[2*p][0]=r[0]; bh[2*p][1]=r[1]; bh[2*p+1][0]=r[2]; bh[2*p+1][1]=r[3];
        }
#pragma unroll
        for (int mt = 0; mt < 2; mt++) {
            uint32_t ah[4], al[4];
            uint32_t ao = (uint32_t)(mt * 16 * A_STRIDE + ks * 32);
            ldsm4(ah, aHi + ao);
            ldsm4(al, aLo + ao);
#pragma unroll
            for (int nt = 0; nt < 8; nt++) mmaf16(acc[mt][nt], ah, bh[nt]);
#pragma unroll
            for (int nt = 0; nt < 8; nt++) mmaf16(acc[mt][nt], al, bh[nt]);
        }
    }
    __syncthreads();   // before epilogue rewrites A
}

// bias + relu + fp16 hi/lo split -> A smem
__device__ __forceinline__ void epi256(char* sm, float acc[2][8][4], int tid) {
    const int lane = tid & 31, wid = tid >> 5, wm = wid >> 2, wn = wid & 3;
    const float* bias_s = (const float*)(sm + OFF_BIAS);
    const int r0 = wm * 32 + (lane >> 2);
    const int c0 = wn * 64 + (lane & 3) * 2;
#pragma unroll
    for (int mt = 0; mt < 2; mt++)
#pragma unroll
    for (int nt = 0; nt < 8; nt++) {
        int col = c0 + nt * 8;
        float b0 = bias_s[col], b1 = bias_s[col + 1];
        float v0 = fmaxf(acc[mt][nt][0] + b0, 0.f);
        float v1 = fmaxf(acc[mt][nt][1] + b1, 0.f);
        float v2 = fmaxf(acc[mt][nt][2] + b0, 0.f);
        float v3 = fmaxf(acc[mt][nt][3] + b1, 0.f);
        unsigned short h0,h1,h2,h3,l0,l1,l2,l3;
        split2h(v0,h0,l0); split2h(v1,h1,l1); split2h(v2,h2,l2); split2h(v3,h3,l3);
        uint32_t h01 = (uint32_t)h0 | ((uint32_t)h1 << 16);
        uint32_t l01 = (uint32_t)l0 | ((uint32_t)l1 << 16);
        uint32_t h23 = (uint32_t)h2 | ((uint32_t)h3 << 16);
        uint32_t l23 = (uint32_t)l2 | ((uint32_t)l3 << 16);
        int rowi = r0 + mt * 16;
        *(uint32_t*)(sm + OFF_A_HI + rowi * A_STRIDE + col * 2) = h01;
        *(uint32_t*)(sm + OFF_A_LO + rowi * A_STRIDE + col * 2) = l01;
        *(uint32_t*)(sm + OFF_A_HI + (rowi + 8) * A_STRIDE + col * 2) = h23;
        *(uint32_t*)(sm + OFF_A_LO + (rowi + 8) * A_STRIDE + col * 2) = l23;
    }
    __syncthreads();
}

// prologue for the 96-row layer3 (pairs wn<3 own 32 rows each)
__device__ __forceinline__ void prologue96(uint32_t smb, const __half* __restrict__ w, int tid) {
    const int lane = tid & 31, wid = tid >> 5;
    const int wm = wid >> 2, wn = wid & 3;
    if (wn >= 3) return;
    const uint32_t pairbase = smb + OFF_B + (uint32_t)(wn * PAIR_RING);
    const int idx = wm * 32 + lane;          // 0..63
    const int row = idx >> 1, half = idx & 1;
    const uint32_t bdst = pairbase + (uint32_t)(row * B_STRIDE + half * 16);
    const __half* src = w + (wn*32 + row) * 256 + half * 8;
    cp16(bdst, src);              CP_COMMIT();
    cp16(bdst + BSTG, src + 16);  CP_COMMIT();
}

// 64x96x256 layer mainloop (reg layer3, N padded to 96).
__device__ __forceinline__ void gemm96(char* sm, uint32_t smb,
    const __half* __restrict__ w, float acc[2][4][4], int tid)
{
    const int lane = tid & 31, wid = tid >> 5;
    const int wm = wid >> 2, wn = wid & 3;
    if (wn >= 3) { __syncthreads(); return; }
    const int a_row  = (lane & 7) + ((lane >> 3) & 1) * 8;
    const int a_koff = (lane >> 4) * 8;
    const int b_n    = (lane & 7) + ((lane >> 4) << 3);
    const int b_koff = ((lane >> 3) & 1) * 8;
    const int barid  = 1 + wn;

    const uint32_t aHi = smb + OFF_A_HI + (uint32_t)((wm*32 + a_row) * A_STRIDE + a_koff * 2);
    const uint32_t aLo = aHi + (OFF_A_LO - OFF_A_HI);
    const uint32_t pairbase = smb + OFF_B + (uint32_t)(wn * PAIR_RING);
    const uint32_t bOff = (uint32_t)(b_n * B_STRIDE + b_koff * 2);

    const int idx = wm * 32 + lane;          // 0..63
    const int row = idx >> 1, half = idx & 1;
    const uint32_t bdst = pairbase + (uint32_t)(row * B_STRIDE + half * 16);
    const __half* src = w + (wn*32 + row) * 256 + half * 8;

    int st_rd = 0, st_wr = 2;
    for (int ks = 0; ks < 16; ks++) {
        CP_WAIT1();
        bar_pair(barid);
        if (ks + 2 < 16)
            cp16(bdst + (uint32_t)(st_wr * BSTG), src + (ks + 2) * 16);
        CP_COMMIT();

        const uint32_t bb = pairbase + (uint32_t)(st_rd * BSTG) + bOff;
        st_rd = (st_rd == 2) ? 0 : st_rd + 1;
        st_wr = (st_wr == 2) ? 0 : st_wr + 1;

        uint32_t bh[4][2];
#pragma unroll
        for (int p = 0; p < 2; p++) {
            uint32_t r[4];
            ldsm4(r, bb + p * (16 * B_STRIDE));
            bh[2*p][0]=r[0]; bh[2*p][1]=r[1]; bh[2*p+1][0]=r[2]; bh[2*p+1][1]=r[3];
        }
#pragma unroll
        for (int mt = 0; mt < 2; mt++) {
            uint32_t ah[4], al[4];
            uint32_t ao = (uint32_t)(mt * 16 * A_STRIDE + ks * 32);
            ldsm4(ah, aHi + ao);
            ldsm4(al, aLo + ao);
#pragma unroll
            for (int nt = 0; nt < 4; nt++) mmaf16(acc[mt][nt], ah, bh[nt]);
#pragma unroll
            for (int nt = 0; nt < 4; nt++) mmaf16(acc[mt][nt], al, bh[nt]);
        }
    }
    __syncthreads();
}

// ---------------- main kernel ----------------
__global__ void __launch_bounds__(THREADS, 2) gfocal_mma_kernel(
    const float* __restrict__ x,
    const float* __restrict__ cb1, const float* __restrict__ cb2,
    const float* __restrict__ cw3, const float* __restrict__ cb3,
    const float* __restrict__ rb1, const float* __restrict__ rb2,
    const float* __restrict__ rb3,
    const float* __restrict__ qw1, const float* __restrict__ qb1,
    const float* __restrict__ qw2, const float* __restrict__ qb2,
    float* __restrict__ cls_out, float* __restrict__ box_out,
    float* __restrict__ reg_out)
{
    extern __shared__ char sm[];
    const uint32_t smb = smem_u32(sm);
    const int tid  = threadIdx.x;
    const int base = blockIdx.x * BM;

    float* bias_s = (float*)(sm + OFF_BIAS);
    float* stat_s = (float*)(sm + OFF_STAT);
    float* stage  = (float*)(sm + OFF_STAGE);
    float* qw1_s  = (float*)(sm + OFF_QW1);
    float* p1_s   = (float*)(sm + OFF_P1);
    float* p2_s   = (float*)(sm + OFF_P2);

    float acc[2][8][4];

    // ================= REG branch =================
    prologue256(smb, g_wh[0], tid);            // overlaps x load/split
    if (tid < 256) bias_s[tid] = rb1[tid];
    load_x_split(sm, x + (size_t)base * 256, tid);
    __syncthreads();
#pragma unroll
    for (int i = 0; i < 64; i++) ((float*)acc)[i] = 0.f;
    gemm256(sm, smb, g_wh[0], acc, tid);
    prologue256(smb, g_wh[1], tid);            // overlaps epilogue
    epi256(sm, acc, tid);

    if (tid < 256) bias_s[tid] = rb2[tid];
#pragma unroll
    for (int i = 0; i < 64; i++) ((float*)acc)[i] = 0.f;
    gemm256(sm, smb, g_wh[1], acc, tid);
    prologue96(smb, g_w3h, tid);               // overlaps epilogue
    epi256(sm, acc, tid);

    if (tid < 68) bias_s[tid] = rb3[tid];
    __syncthreads();
    {
        float acc3[2][4][4];
#pragma unroll
        for (int i = 0; i < 32; i++) ((float*)acc3)[i] = 0.f;
        gemm96(sm, smb, g_w3h, acc3, tid);
        const int lane = tid & 31, wid = tid >> 5;
        const int wm = wid >> 2, wn = wid & 3;
        if (wn < 3) {
            const int r0 = wm * 32 + (lane >> 2);
            const int cb = (lane & 3) * 2;
#pragma unroll
            for (int mt = 0; mt < 2; mt++)
#pragma unroll
            for (int nt = 0; nt < 4; nt++) {
                int col = wn * 32 + nt * 8 + cb;
                if (col < 68) {
                    int r = r0 + mt * 16;
                    float b0 = bias_s[col], b1 = bias_s[col + 1];
                    stage[r * 76 + col]       = acc3[mt][nt][0] + b0;
                    stage[r * 76 + col + 1]   = acc3[mt][nt][1] + b1;
                    stage[(r+8) * 76 + col]   = acc3[mt][nt][2] + b0;
                    stage[(r+8) * 76 + col+1] = acc3[mt][nt][3] + b1;
                }
            }
        }
    }
    __syncthreads();

    // per-(token,side) epilogue: softmax / integral / top4 stats — 256-way
    {
        const int m = tid >> 2, g = tid & 3;
        float lg[17];
#pragma unroll
        for (int j = 0; j < 17; j++) lg[j] = stage[m * 76 + g * 17 + j];
        float mx = lg[0];
#pragma unroll
        for (int j = 1; j < 17; j++) mx = fmaxf(mx, lg[j]);
        float e[17], s = 0.f, si = 0.f;
#pragma unroll
        for (int j = 0; j < 17; j++) {
            e[j] = __expf(lg[j] - mx);
            s += e[j]; si += e[j] * (float)j;
        }
        box_out[(size_t)(base + m) * 4 + g] = si / (s * 16.0f);
        float inv = 1.0f / s, tsum = 0.f;
#pragma unroll
        for (int t4 = 0; t4 < 4; t4++) {
            float mv = -1.0f; int mi = 0;
#pragma unroll
            for (int j = 0; j < 17; j++)
                if (e[j] > mv) { mv = e[j]; mi = j; }
            float tv = mv * inv;
            stat_s[m * 20 + g * 5 + t4] = tv;
            tsum += tv;
            e[mi] = -1.0f;
        }
        stat_s[m * 20 + g * 5 + 4] = tsum * 0.25f;
    }
    for (int idx = tid; idx < 64 * 68; idx += THREADS) {
        int row = idx / 68;
        int col = idx - row * 68;
        reg_out[(size_t)base * 68 + idx] = stage[row * 76 + col];
    }
    __syncthreads();   // stage (aliases B region) fully read before CLS prologue

    // ================= CLS branch =================
    prologue256(smb, g_wh[2], tid);            // overlaps x reload/split
    if (tid < 256) bias_s[tid] = cb1[tid];
    load_x_split(sm, x + (size_t)base * 256, tid);
    __syncthreads();
#pragma unroll
    for (int i = 0; i < 64; i++) ((float*)acc)[i] = 0.f;
    gemm256(sm, smb, g_wh[2], acc, tid);
    prologue256(smb, g_wh[3], tid);            // overlaps epilogue
    epi256(sm, acc, tid);

    if (tid < 256) bias_s[tid] = cb2[tid];
#pragma unroll
    for (int i = 0; i < 64; i++) ((float*)acc)[i] = 0.f;
    gemm256(sm, smb, g_wh[3], acc, tid);
    epi256(sm, acc, tid);

    // cls layer3 partials (4-way K split) + qw1 smem load
    {
        const int m = tid & 63, qtr = tid >> 6;
        const char* pa = sm + OFF_A_HI + m * A_STRIDE;
        float p = 0.0f;
        const int k_begin = qtr * 64;
        for (int k0 = k_begin; k0 < k_begin + 64; k0 += 8) {
            uint4 uh = *(const uint4*)(pa + k0 * 2);
            uint4 ul = *(const uint4*)(pa + (OFF_A_LO - OFF_A_HI) + k0 * 2);
            float4 w0 = *(const float4*)(cw3 + k0);
            float4 w1 = *(const float4*)(cw3 + k0 + 4);
            const uint32_t* ph = (const uint32_t*)&uh;
            const uint32_t* pl = (const uint32_t*)&ul;
            float wv[8] = {w0.x,w0.y,w0.z,w0.w,w1.x,w1.y,w1.z,w1.w};
#pragma unroll
            for (int e = 0; e < 8; e++) {
                unsigned short hs = (e & 1) ? (unsigned short)(ph[e>>1] >> 16) : (unsigned short)(ph[e>>1] & 0xffff);
                unsigned short ls = (e & 1) ? (unsigned short)(pl[e>>1] >> 16) : (unsigned short)(pl[e>>1] & 0xffff);
                p = fmaf(h2f(hs) + h2f(ls), wv[e], p);
            }
        }
        p1_s[tid] = p;
    }
    for (int idx = tid; idx < 64 * 20; idx += THREADS) qw1_s[idx] = qw1[idx];
    __syncthreads();

    // quality head partials (4-way O split)
    {
        const int m = tid & 63, ch = tid >> 6;
        const float* st = stat_s + m * 20;
        float qp = 0.0f;
        for (int o = ch * 16; o < ch * 16 + 16; o++) {
            float hsum = qb1[o];
#pragma unroll
            for (int c = 0; c < 20; c++)
                hsum = fmaf(qw1_s[o * 20 + c], st[c], hsum);
            qp = fmaf(fmaxf(hsum, 0.0f), qw2[o], qp);
        }
        p2_s[tid] = qp;
    }
    __syncthreads();

    if (tid < 64) {
        float sacc = cb3[0] + p1_s[tid] + p1_s[tid+64] + p1_s[tid+128] + p1_s[tid+192];
        float q    = qb2[0] + p2_s[tid] + p2_s[tid+64] + p2_s[tid+128] + p2_s[tid+192];
        cls_out[base + tid] = sigmoidf_(sacc) * sigmoidf_(q);
    }
}

extern "C" void kernel_launch(void* const* d_in, const int* in_sizes, int n_in,
                              void* d_out, int out_size)
{
    const float* x   = (const float*)d_in[0];
    const float* cw1 = (const float*)d_in[1];
    const float* cb1 = (const float*)d_in[2];
    const float* cw2 = (const float*)d_in[3];
    const float* cb2 = (const float*)d_in[4];
    const float* cw3 = (const float*)d_in[5];
    const float* cb3 = (const float*)d_in[6];
    const float* rw1 = (const float*)d_in[7];
    const float* rb1 = (const float*)d_in[8];
    const float* rw2 = (const float*)d_in[9];
    const float* rb2 = (const float*)d_in[10];
    const float* rw3 = (const float*)d_in[11];
    const float* rb3 = (const float*)d_in[12];
    const float* qw1 = (const float*)d_in[13];
    const float* qb1 = (const float*)d_in[14];
    const float* qw2 = (const float*)d_in[15];
    const float* qb2 = (const float*)d_in[16];

    float* out = (float*)d_out;
    float* cls_out = out;
    float* box_out = out + NTOK;
    float* reg_out = out + NTOK + (size_t)NTOK * 4;

    prep_kernel<<<256, 256>>>(rw1, rw2, cw1, cw2, rw3);

    cudaFuncSetAttribute(gfocal_mma_kernel,
                         cudaFuncAttributeMaxDynamicSharedMemorySize, SMEM_BYTES);
    gfocal_mma_kernel<<<NBLK, THREADS, SMEM_BYTES>>>(
        x, cb1, cb2, cw3, cb3, rb1, rb2, rb3,
        qw1, qb1, qw2, qb2,
        cls_out, box_out, reg_out);
}

// round 10
// speedup vs baseline: 1.2232x; 1.2232x over previous
#include <cuda_runtime.h>
#include <cuda_fp16.h>
#include <stdint.h>

#define NTOK    294912
#define BM      64
#define NBLK    (NTOK / BM)      // 4608
#define THREADS 256

// ---- smem byte offsets ----
#define OFF_A    0               // 64 x 264 fp16 (row stride 528B)
#define OFF_B    33792           // 4 pairs x 3 stages x 3072B
#define PAIR_RING 9216
#define BSTG     3072
#define OFF_STAGE OFF_B          // aliases B: 64 x 76 f32 (19456B)
#define OFF_QW1  (OFF_B + 20480) // 64*20 f32
#define OFF_P1   (OFF_B + 26624) // 256 f32 partials (cls)
#define OFF_P2   (OFF_B + 27648) // 256 f32 partials (quality)
#define OFF_BIAS 70656           // 256 f32
#define OFF_STAT 71680           // 64*20 f32
#define SMEM_BYTES 76800

#define A_STRIDE 528
#define B_STRIDE 48

// fp16 weights, written by prep kernel each launch
__device__ __half g_wh[4][65536];    // 0=rw1 1=rw2 2=cw1 3=cw2
__device__ __half g_w3h[96 * 256];   // rw3 padded to 96 rows

// ---------------- helpers ----------------
__device__ __forceinline__ uint32_t smem_u32(const void* p) {
    uint32_t a;
    asm("{ .reg .u64 t; cvta.to.shared.u64 t, %1; cvt.u32.u64 %0, t; }"
        : "=r"(a) : "l"(p));
    return a;
}
__device__ __forceinline__ void ldsm4(uint32_t* r, uint32_t addr) {
    asm volatile("ldmatrix.sync.aligned.m8n8.x4.shared.b16 {%0,%1,%2,%3}, [%4];"
        : "=r"(r[0]), "=r"(r[1]), "=r"(r[2]), "=r"(r[3]) : "r"(addr));
}
__device__ __forceinline__ void mmaf16(float* c, const uint32_t* a, const uint32_t* b) {
    asm volatile("mma.sync.aligned.m16n8k16.row.col.f32.f16.f16.f32 "
        "{%0,%1,%2,%3}, {%4,%5,%6,%7}, {%8,%9}, {%0,%1,%2,%3};"
        : "+f"(c[0]), "+f"(c[1]), "+f"(c[2]), "+f"(c[3])
        : "r"(a[0]), "r"(a[1]), "r"(a[2]), "r"(a[3]), "r"(b[0]), "r"(b[1]));
}
__device__ __forceinline__ void cp16(uint32_t dst, const void* src) {
    asm volatile("cp.async.cg.shared.global [%0], [%1], 16;" :: "r"(dst), "l"(src));
}
#define CP_COMMIT() asm volatile("cp.async.commit_group;" ::: "memory")
#define CP_WAIT1()  asm volatile("cp.async.wait_group 1;" ::: "memory")
__device__ __forceinline__ void bar_pair(int id) {
    asm volatile("bar.sync %0, 64;" :: "r"(id) : "memory");
}
__device__ __forceinline__ float sigmoidf_(float v) { return 1.0f / (1.0f + __expf(-v)); }

// ---------------- prep kernel: weights -> fp16 ----------------
__global__ void prep_kernel(const float* rw1, const float* rw2,
                            const float* cw1, const float* cw2,
                            const float* rw3) {
    int i = blockIdx.x * 256 + threadIdx.x;
    if (i < 65536) {
        g_wh[0][i] = __float2half_rn(rw1[i]);
        g_wh[1][i] = __float2half_rn(rw2[i]);
        g_wh[2][i] = __float2half_rn(cw1[i]);
        g_wh[3][i] = __float2half_rn(cw2[i]);
        if (i < 96 * 256) {
            int row = i >> 8;
            g_w3h[i] = __float2half_rn((row < 68) ? rw3[i] : 0.0f);
        }
    }
}

// ---------------- device subroutines ----------------
__device__ __forceinline__ void load_x_h(char* sm, const float* xg, int tid) {
    for (int idx = tid; idx < 4096; idx += THREADS) {
        int row = idx >> 6;
        int c4  = (idx & 63) << 2;
        float4 v = *(const float4*)(xg + row * 256 + c4);
        __half2 h01 = __floats2half2_rn(v.x, v.y);
        __half2 h23 = __floats2half2_rn(v.z, v.w);
        uint2 uh;
        uh.x = *(uint32_t*)&h01;
        uh.y = *(uint32_t*)&h23;
        *(uint2*)(sm + OFF_A + row * A_STRIDE + c4 * 2) = uh;
    }
}

// issue first 2 B slices of a 256-row layer (hoistable across serial regions)
__device__ __forceinline__ void prologue256(uint32_t smb, const __half* __restrict__ w, int tid) {
    const int lane = tid & 31, wid = tid >> 5;
    const int wm = wid >> 2, wn = wid & 3;
    const uint32_t pairbase = smb + OFF_B + (uint32_t)(wn * PAIR_RING);
    const uint32_t bdst = pairbase + (uint32_t)((wm*32 + lane) * B_STRIDE);
    const __half* src = w + (wn*64 + wm*32 + lane) * 256;
    cp16(bdst, src);               cp16(bdst + 16, src + 8);               CP_COMMIT();
    cp16(bdst + BSTG, src + 16);   cp16(bdst + BSTG + 16, src + 24);       CP_COMMIT();
}

// 64x256x256 layer mainloop. Per-pair private 3-stage ring; pair-local barriers.
// REQUIRES prologue256(w) already issued with matching commit cadence.
__device__ __forceinline__ void gemm256(char* sm, uint32_t smb,
    const __half* __restrict__ w, float acc[2][8][4], int tid)
{
    const int lane = tid & 31, wid = tid >> 5;
    const int wm = wid >> 2, wn = wid & 3;
    const int a_row  = (lane & 7) + ((lane >> 3) & 1) * 8;
    const int a_koff = (lane >> 4) * 8;
    const int b_n    = (lane & 7) + ((lane >> 4) << 3);
    const int b_koff = ((lane >> 3) & 1) * 8;
    const int barid  = 1 + wn;

    const uint32_t aB = smb + OFF_A + (uint32_t)((wm*32 + a_row) * A_STRIDE + a_koff * 2);
    const uint32_t pairbase = smb + OFF_B + (uint32_t)(wn * PAIR_RING);
    const uint32_t bOff = (uint32_t)(b_n * B_STRIDE + b_koff * 2);

    const uint32_t bdst = pairbase + (uint32_t)((wm*32 + lane) * B_STRIDE);
    const __half* src = w + (wn*64 + wm*32 + lane) * 256;

    int st_rd = 0, st_wr = 2;
    for (int ks = 0; ks < 16; ks++) {
        CP_WAIT1();
        bar_pair(barid);
        if (ks + 2 < 16) {
            uint32_t d2 = bdst + (uint32_t)(st_wr * BSTG);
            const __half* s2 = src + (ks + 2) * 16;
            cp16(d2, s2);
            cp16(d2 + 16, s2 + 8);
        }
        CP_COMMIT();

        const uint32_t bb = pairbase + (uint32_t)(st_rd * BSTG) + bOff;
        st_rd = (st_rd == 2) ? 0 : st_rd + 1;
        st_wr = (st_wr == 2) ? 0 : st_wr + 1;

        uint32_t bh[8][2];
#pragma unroll
        for (int p = 0; p < 4; p++) {
            uint32_t r[4];
            ldsm4(r, bb + p * (16 * B_STRIDE));
            bh[2*p][0]=r[0]; bh[2*p][1]=r[1]; bh[2*p+1][0]=r[2]; bh[2*p+1][1]=r[3];
        }
#pragma unroll
        for (int mt = 0; mt < 2; mt++) {
            uint32_t ah[4];
            uint32_t ao = (uint32_t)(mt * 16 * A_STRIDE + ks * 32);
            ldsm4(ah, aB + ao);
#pragma unroll
            for (int nt = 0; nt < 8; nt++) mmaf16(acc[mt][nt], ah, bh[nt]);
        }
    }
    __syncthreads();   // before epilogue rewrites A
}

// bias + relu + fp16 round -> A smem
__device__ __forceinline__ void epi256(char* sm, float acc[2][8][4], int tid) {
    const int lane = tid & 31, wid = tid >> 5, wm = wid >> 2, wn = wid & 3;
    const float* bias_s = (const float*)(sm + OFF_BIAS);
    const int r0 = wm * 32 + (lane >> 2);
    const int c0 = wn * 64 + (lane & 3) * 2;
#pragma unroll
    for (int mt = 0; mt < 2; mt++)
#pragma unroll
    for (int nt = 0; nt < 8; nt++) {
        int col = c0 + nt * 8;
        float b0 = bias_s[col], b1 = bias_s[col + 1];
        float v0 = fmaxf(acc[mt][nt][0] + b0, 0.f);
        float v1 = fmaxf(acc[mt][nt][1] + b1, 0.f);
        float v2 = fmaxf(acc[mt][nt][2] + b0, 0.f);
        float v3 = fmaxf(acc[mt][nt][3] + b1, 0.f);
        __half2 p01 = __floats2half2_rn(v0, v1);
        __half2 p23 = __floats2half2_rn(v2, v3);
        int rowi = r0 + mt * 16;
        *(uint32_t*)(sm + OFF_A + rowi * A_STRIDE + col * 2) = *(uint32_t*)&p01;
        *(uint32_t*)(sm + OFF_A + (rowi + 8) * A_STRIDE + col * 2) = *(uint32_t*)&p23;
    }
    __syncthreads();
}

// prologue for the 96-row layer3 (pairs wn<3 own 32 rows each)
__device__ __forceinline__ void prologue96(uint32_t smb, const __half* __restrict__ w, int tid) {
    const int lane = tid & 31, wid = tid >> 5;
    const int wm = wid >> 2, wn = wid & 3;
    if (wn >= 3) return;
    const uint32_t pairbase = smb + OFF_B + (uint32_t)(wn * PAIR_RING);
    const int idx = wm * 32 + lane;          // 0..63
    const int row = idx >> 1, half = idx & 1;
    const uint32_t bdst = pairbase + (uint32_t)(row * B_STRIDE + half * 16);
    const __half* src = w + (wn*32 + row) * 256 + half * 8;
    cp16(bdst, src);              CP_COMMIT();
    cp16(bdst + BSTG, src + 16);  CP_COMMIT();
}

// 64x96x256 layer mainloop (reg layer3, N padded to 96).
__device__ __forceinline__ void gemm96(char* sm, uint32_t smb,
    const __half* __restrict__ w, float acc[2][4][4], int tid)
{
    const int lane = tid & 31, wid = tid >> 5;
    const int wm = wid >> 2, wn = wid & 3;
    if (wn >= 3) { __syncthreads(); return; }
    const int a_row  = (lane & 7) + ((lane >> 3) & 1) * 8;
    const int a_koff = (lane >> 4) * 8;
    const int b_n    = (lane & 7) + ((lane >> 4) << 3);
    const int b_koff = ((lane >> 3) & 1) * 8;
    const int barid  = 1 + wn;

    const uint32_t aB = smb + OFF_A + (uint32_t)((wm*32 + a_row) * A_STRIDE + a_koff * 2);
    const uint32_t pairbase = smb + OFF_B + (uint32_t)(wn * PAIR_RING);
    const uint32_t bOff = (uint32_t)(b_n * B_STRIDE + b_koff * 2);

    const int idx = wm * 32 + lane;          // 0..63
    const int row = idx >> 1, half = idx & 1;
    const uint32_t bdst = pairbase + (uint32_t)(row * B_STRIDE + half * 16);
    const __half* src = w + (wn*32 + row) * 256 + half * 8;

    int st_rd = 0, st_wr = 2;
    for (int ks = 0; ks < 16; ks++) {
        CP_WAIT1();
        bar_pair(barid);
        if (ks + 2 < 16)
            cp16(bdst + (uint32_t)(st_wr * BSTG), src + (ks + 2) * 16);
        CP_COMMIT();

        const uint32_t bb = pairbase + (uint32_t)(st_rd * BSTG) + bOff;
        st_rd = (st_rd == 2) ? 0 : st_rd + 1;
        st_wr = (st_wr == 2) ? 0 : st_wr + 1;

        uint32_t bh[4][2];
#pragma unroll
        for (int p = 0; p < 2; p++) {
            uint32_t r[4];
            ldsm4(r, bb + p * (16 * B_STRIDE));
            bh[2*p][0]=r[0]; bh[2*p][1]=r[1]; bh[2*p+1][0]=r[2]; bh[2*p+1][1]=r[3];
        }
#pragma unroll
        for (int mt = 0; mt < 2; mt++) {
            uint32_t ah[4];
            uint32_t ao = (uint32_t)(mt * 16 * A_STRIDE + ks * 32);
            ldsm4(ah, aB + ao);
#pragma unroll
            for (int nt = 0; nt < 4; nt++) mmaf16(acc[mt][nt], ah, bh[nt]);
        }
    }
    __syncthreads();
}

// ---------------- main kernel ----------------
__global__ void __launch_bounds__(THREADS, 2) gfocal_mma_kernel(
    const float* __restrict__ x,
    const float* __restrict__ cb1, const float* __restrict__ cb2,
    const float* __restrict__ cw3, const float* __restrict__ cb3,
    const float* __restrict__ rb1, const float* __restrict__ rb2,
    const float* __restrict__ rb3,
    const float* __restrict__ qw1, const float* __restrict__ qb1,
    const float* __restrict__ qw2, const float* __restrict__ qb2,
    float* __restrict__ cls_out, float* __restrict__ box_out,
    float* __restrict__ reg_out)
{
    extern __shared__ char sm[];
    const uint32_t smb = smem_u32(sm);
    const int tid  = threadIdx.x;
    const int base = blockIdx.x * BM;

    float* bias_s = (float*)(sm + OFF_BIAS);
    float* stat_s = (float*)(sm + OFF_STAT);
    float* stage  = (float*)(sm + OFF_STAGE);
    float* qw1_s  = (float*)(sm + OFF_QW1);
    float* p1_s   = (float*)(sm + OFF_P1);
    float* p2_s   = (float*)(sm + OFF_P2);

    float acc[2][8][4];

    // ================= REG branch =================
    prologue256(smb, g_wh[0], tid);            // overlaps x load
    if (tid < 256) bias_s[tid] = rb1[tid];
    load_x_h(sm, x + (size_t)base * 256, tid);
    __syncthreads();
#pragma unroll
    for (int i = 0; i < 64; i++) ((float*)acc)[i] = 0.f;
    gemm256(sm, smb, g_wh[0], acc, tid);
    prologue256(smb, g_wh[1], tid);            // overlaps epilogue
    epi256(sm, acc, tid);

    if (tid < 256) bias_s[tid] = rb2[tid];
#pragma unroll
    for (int i = 0; i < 64; i++) ((float*)acc)[i] = 0.f;
    gemm256(sm, smb, g_wh[1], acc, tid);
    prologue96(smb, g_w3h, tid);               // overlaps epilogue
    epi256(sm, acc, tid);

    if (tid < 68) bias_s[tid] = rb3[tid];
    __syncthreads();
    {
        float acc3[2][4][4];
#pragma unroll
        for (int i = 0; i < 32; i++) ((float*)acc3)[i] = 0.f;
        gemm96(sm, smb, g_w3h, acc3, tid);
        const int lane = tid & 31, wid = tid >> 5;
        const int wm = wid >> 2, wn = wid & 3;
        if (wn < 3) {
            const int r0 = wm * 32 + (lane >> 2);
            const int cb = (lane & 3) * 2;
#pragma unroll
            for (int mt = 0; mt < 2; mt++)
#pragma unroll
            for (int nt = 0; nt < 4; nt++) {
                int col = wn * 32 + nt * 8 + cb;
                if (col < 68) {
                    int r = r0 + mt * 16;
                    float b0 = bias_s[col], b1 = bias_s[col + 1];
                    stage[r * 76 + col]       = acc3[mt][nt][0] + b0;
                    stage[r * 76 + col + 1]   = acc3[mt][nt][1] + b1;
                    stage[(r+8) * 76 + col]   = acc3[mt][nt][2] + b0;
                    stage[(r+8) * 76 + col+1] = acc3[mt][nt][3] + b1;
                }
            }
        }
    }
    __syncthreads();

    // per-(token,side) epilogue: softmax / integral / top4 stats — 256-way
    {
        const int m = tid >> 2, g = tid & 3;
        float lg[17];
#pragma unroll
        for (int j = 0; j < 17; j++) lg[j] = stage[m * 76 + g * 17 + j];
        float mx = lg[0];
#pragma unroll
        for (int j = 1; j < 17; j++) mx = fmaxf(mx, lg[j]);
        float e[17], s = 0.f, si = 0.f;
#pragma unroll
        for (int j = 0; j < 17; j++) {
            e[j] = __expf(lg[j] - mx);
            s += e[j]; si += e[j] * (float)j;
        }
        box_out[(size_t)(base + m) * 4 + g] = si / (s * 16.0f);
        float inv = 1.0f / s, tsum = 0.f;
#pragma unroll
        for (int t4 = 0; t4 < 4; t4++) {
            float mv = -1.0f; int mi = 0;
#pragma unroll
            for (int j = 0; j < 17; j++)
                if (e[j] > mv) { mv = e[j]; mi = j; }
            float tv = mv * inv;
            stat_s[m * 20 + g * 5 + t4] = tv;
            tsum += tv;
            e[mi] = -1.0f;
        }
        stat_s[m * 20 + g * 5 + 4] = tsum * 0.25f;
    }
    for (int idx = tid; idx < 64 * 68; idx += THREADS) {
        int row = idx / 68;
        int col = idx - row * 68;
        reg_out[(size_t)base * 68 + idx] = stage[row * 76 + col];
    }
    __syncthreads();   // stage (aliases B region) fully read before CLS prologue

    // ================= CLS branch =================
    prologue256(smb, g_wh[2], tid);            // overlaps x reload
    if (tid < 256) bias_s[tid] = cb1[tid];
    load_x_h(sm, x + (size_t)base * 256, tid);
    __syncthreads();
#pragma unroll
    for (int i = 0; i < 64; i++) ((float*)acc)[i] = 0.f;
    gemm256(sm, smb, g_wh[2], acc, tid);
    prologue256(smb, g_wh[3], tid);            // overlaps epilogue
    epi256(sm, acc, tid);

    if (tid < 256) bias_s[tid] = cb2[tid];
#pragma unroll
    for (int i = 0; i < 64; i++) ((float*)acc)[i] = 0.f;
    gemm256(sm, smb, g_wh[3], acc, tid);
    epi256(sm, acc, tid);

    // cls layer3 partials (4-way K split) + qw1 smem load
    {
        const int m = tid & 63, qtr = tid >> 6;
        const char* pa = sm + OFF_A + m * A_STRIDE;
        float p = 0.0f;
        const int k_begin = qtr * 64;
        for (int k0 = k_begin; k0 < k_begin + 64; k0 += 8) {
            uint4 uh = *(const uint4*)(pa + k0 * 2);
            float4 w0 = *(const float4*)(cw3 + k0);
            float4 w1 = *(const float4*)(cw3 + k0 + 4);
            const __half2* ph = (const __half2*)&uh;
            float wv[8] = {w0.x,w0.y,w0.z,w0.w,w1.x,w1.y,w1.z,w1.w};
#pragma unroll
            for (int e2 = 0; e2 < 4; e2++) {
                float2 hv = __half22float2(ph[e2]);
                p = fmaf(hv.x, wv[e2*2],   p);
                p = fmaf(hv.y, wv[e2*2+1], p);
            }
        }
        p1_s[tid] = p;
    }
    for (int idx = tid; idx < 64 * 20; idx += THREADS) qw1_s[idx] = qw1[idx];
    __syncthreads();

    // quality head partials (4-way O split)
    {
        const int m = tid & 63, ch = tid >> 6;
        const float* st = stat_s + m * 20;
        float qp = 0.0f;
        for (int o = ch * 16; o < ch * 16 + 16; o++) {
            float hsum = qb1[o];
#pragma unroll
            for (int c = 0; c < 20; c++)
                hsum = fmaf(qw1_s[o * 20 + c], st[c], hsum);
            qp = fmaf(fmaxf(hsum, 0.0f), qw2[o], qp);
        }
        p2_s[tid] = qp;
    }
    __syncthreads();

    if (tid < 64) {
        float sacc = cb3[0] + p1_s[tid] + p1_s[tid+64] + p1_s[tid+128] + p1_s[tid+192];
        float q    = qb2[0] + p2_s[tid] + p2_s[tid+64] + p2_s[tid+128] + p2_s[tid+192];
        cls_out[base + tid] = sigmoidf_(sacc) * sigmoidf_(q);
    }
}

extern "C" void kernel_launch(void* const* d_in, const int* in_sizes, int n_in,
                              void* d_out, int out_size)
{
    const float* x   = (const float*)d_in[0];
    const float* cw1 = (const float*)d_in[1];
    const float* cb1 = (const float*)d_in[2];
    const float* cw2 = (const float*)d_in[3];
    const float* cb2 = (const float*)d_in[4];
    const float* cw3 = (const float*)d_in[5];
    const float* cb3 = (const float*)d_in[6];
    const float* rw1 = (const float*)d_in[7];
    const float* rb1 = (const float*)d_in[8];
    const float* rw2 = (const float*)d_in[9];
    const float* rb2 = (const float*)d_in[10];
    const float* rw3 = (const float*)d_in[11];
    const float* rb3 = (const float*)d_in[12];
    const float* qw1 = (const float*)d_in[13];
    const float* qb1 = (const float*)d_in[14];
    const float* qw2 = (const float*)d_in[15];
    const float* qb2 = (const float*)d_in[16];

    float* out = (float*)d_out;
    float* cls_out = out;
    float* box_out = out + NTOK;
    float* reg_out = out + NTOK + (size_t)NTOK * 4;

    prep_kernel<<<256, 256>>>(rw1, rw2, cw1, cw2, rw3);

    cudaFuncSetAttribute(gfocal_mma_kernel,
                         cudaFuncAttributeMaxDynamicSharedMemorySize, SMEM_BYTES);
    gfocal_mma_kernel<<<NBLK, THREADS, SMEM_BYTES>>>(
        x, cb1, cb2, cw3, cb3, rb1, rb2, rb3,
        qw1, qb1, qw2, qb2,
        cls_out, box_out, reg_out);
}

// round 11
// speedup vs baseline: 1.2479x; 1.0202x over previous
#include <cuda_runtime.h>
#include <cuda_fp16.h>
#include <stdint.h>

#define NTOK    294912
#define BM      64
#define NBLK    (NTOK / BM)      // 4608
#define THREADS 256

// ---- smem byte offsets ----
#define OFF_A    0               // 64 x 264 fp16 (row stride 528B)
#define OFF_B    33792           // 4 pairs x 4 stages x 3072B
#define PAIR_RING 12288
#define BSTG     3072
#define OFF_STAGE OFF_B          // aliases B: 64 x 76 f32 (19456B)
#define OFF_QW1  (OFF_B + 20480) // 64*20 f32
#define OFF_P1   (OFF_B + 26624) // 256 f32 partials (cls)
#define OFF_P2   (OFF_B + 27648) // 256 f32 partials (quality)
#define OFF_BIAS 82944           // 256 f32
#define OFF_STAT 83968           // 64*20 f32
#define SMEM_BYTES 89088

#define A_STRIDE 528
#define B_STRIDE 48

// fp16 weights, written by prep kernel each launch
__device__ __half g_wh[4][65536];    // 0=rw1 1=rw2 2=cw1 3=cw2
__device__ __half g_w3h[96 * 256];   // rw3 padded to 96 rows

// ---------------- helpers ----------------
__device__ __forceinline__ uint32_t smem_u32(const void* p) {
    uint32_t a;
    asm("{ .reg .u64 t; cvta.to.shared.u64 t, %1; cvt.u32.u64 %0, t; }"
        : "=r"(a) : "l"(p));
    return a;
}
__device__ __forceinline__ void ldsm4(uint32_t* r, uint32_t addr) {
    asm volatile("ldmatrix.sync.aligned.m8n8.x4.shared.b16 {%0,%1,%2,%3}, [%4];"
        : "=r"(r[0]), "=r"(r[1]), "=r"(r[2]), "=r"(r[3]) : "r"(addr));
}
__device__ __forceinline__ void mmaf16(float* c, const uint32_t* a, const uint32_t* b) {
    asm volatile("mma.sync.aligned.m16n8k16.row.col.f32.f16.f16.f32 "
        "{%0,%1,%2,%3}, {%4,%5,%6,%7}, {%8,%9}, {%0,%1,%2,%3};"
        : "+f"(c[0]), "+f"(c[1]), "+f"(c[2]), "+f"(c[3])
        : "r"(a[0]), "r"(a[1]), "r"(a[2]), "r"(a[3]), "r"(b[0]), "r"(b[1]));
}
__device__ __forceinline__ void cp16(uint32_t dst, const void* src) {
    asm volatile("cp.async.cg.shared.global [%0], [%1], 16;" :: "r"(dst), "l"(src));
}
#define CP_COMMIT() asm volatile("cp.async.commit_group;" ::: "memory")
#define CP_WAIT2()  asm volatile("cp.async.wait_group 2;" ::: "memory")
__device__ __forceinline__ void bar_pair(int id) {
    asm volatile("bar.sync %0, 64;" :: "r"(id) : "memory");
}
__device__ __forceinline__ float sigmoidf_(float v) { return 1.0f / (1.0f + __expf(-v)); }

// ---------------- prep kernel: weights -> fp16 ----------------
__global__ void prep_kernel(const float* rw1, const float* rw2,
                            const float* cw1, const float* cw2,
                            const float* rw3) {
    int i = blockIdx.x * 256 + threadIdx.x;
    if (i < 65536) {
        g_wh[0][i] = __float2half_rn(rw1[i]);
        g_wh[1][i] = __float2half_rn(rw2[i]);
        g_wh[2][i] = __float2half_rn(cw1[i]);
        g_wh[3][i] = __float2half_rn(cw2[i]);
        if (i < 96 * 256) {
            int row = i >> 8;
            g_w3h[i] = __float2half_rn((row < 68) ? rw3[i] : 0.0f);
        }
    }
}

// ---------------- device subroutines ----------------
__device__ __forceinline__ void load_x_h(char* sm, const float* xg, int tid) {
    for (int idx = tid; idx < 4096; idx += THREADS) {
        int row = idx >> 6;
        int c4  = (idx & 63) << 2;
        float4 v = *(const float4*)(xg + row * 256 + c4);
        __half2 h01 = __floats2half2_rn(v.x, v.y);
        __half2 h23 = __floats2half2_rn(v.z, v.w);
        uint2 uh;
        uh.x = *(uint32_t*)&h01;
        uh.y = *(uint32_t*)&h23;
        *(uint2*)(sm + OFF_A + row * A_STRIDE + c4 * 2) = uh;
    }
}

// issue first 3 B slices of a 256-row layer (hoistable across serial regions)
__device__ __forceinline__ void prologue256(uint32_t smb, const __half* __restrict__ w, int tid) {
    const int lane = tid & 31, wid = tid >> 5;
    const int wm = wid >> 2, wn = wid & 3;
    const uint32_t pairbase = smb + OFF_B + (uint32_t)(wn * PAIR_RING);
    const uint32_t bdst = pairbase + (uint32_t)((wm*32 + lane) * B_STRIDE);
    const __half* src = w + (wn*64 + wm*32 + lane) * 256;
#pragma unroll
    for (int s = 0; s < 3; s++) {
        cp16(bdst + s * BSTG, src + s * 16);
        cp16(bdst + s * BSTG + 16, src + s * 16 + 8);
        CP_COMMIT();
    }
}

// 64x256x256 layer mainloop. 4-stage per-pair ring, prefetch distance 3.
// REQUIRES prologue256(w) already issued (3 commits).
__device__ __forceinline__ void gemm256(char* sm, uint32_t smb,
    const __half* __restrict__ w, float acc[2][8][4], int tid)
{
    const int lane = tid & 31, wid = tid >> 5;
    const int wm = wid >> 2, wn = wid & 3;
    const int a_row  = (lane & 7) + ((lane >> 3) & 1) * 8;
    const int a_koff = (lane >> 4) * 8;
    const int b_n    = (lane & 7) + ((lane >> 4) << 3);
    const int b_koff = ((lane >> 3) & 1) * 8;
    const int barid  = 1 + wn;

    const uint32_t aB = smb + OFF_A + (uint32_t)((wm*32 + a_row) * A_STRIDE + a_koff * 2);
    const uint32_t pairbase = smb + OFF_B + (uint32_t)(wn * PAIR_RING);
    const uint32_t bOff = (uint32_t)(b_n * B_STRIDE + b_koff * 2);

    const uint32_t bdst = pairbase + (uint32_t)((wm*32 + lane) * B_STRIDE);
    const __half* src = w + (wn*64 + wm*32 + lane) * 256;

    for (int ks = 0; ks < 16; ks++) {
        // A loads first: independent of cp.async arrival
        uint32_t ah0[4], ah1[4];
        ldsm4(ah0, aB + (uint32_t)(ks * 32));
        ldsm4(ah1, aB + (uint32_t)(16 * A_STRIDE + ks * 32));

        CP_WAIT2();
        bar_pair(barid);
        if (ks + 3 < 16) {
            uint32_t d2 = bdst + (uint32_t)(((ks + 3) & 3) * BSTG);
            const __half* s2 = src + (ks + 3) * 16;
            cp16(d2, s2);
            cp16(d2 + 16, s2 + 8);
        }
        CP_COMMIT();

        const uint32_t bb = pairbase + (uint32_t)((ks & 3) * BSTG) + bOff;
        uint32_t bh[8][2];
#pragma unroll
        for (int p = 0; p < 4; p++) {
            uint32_t r[4];
            ldsm4(r, bb + p * (16 * B_STRIDE));
            bh[2*p][0]=r[0]; bh[2*p][1]=r[1]; bh[2*p+1][0]=r[2]; bh[2*p+1][1]=r[3];
        }
#pragma unroll
        for (int nt = 0; nt < 8; nt++) mmaf16(acc[0][nt], ah0, bh[nt]);
#pragma unroll
        for (int nt = 0; nt < 8; nt++) mmaf16(acc[1][nt], ah1, bh[nt]);
    }
    __syncthreads();   // before epilogue rewrites A
}

// bias + relu + fp16 round -> A smem
__device__ __forceinline__ void epi256(char* sm, float acc[2][8][4], int tid) {
    const int lane = tid & 31, wid = tid >> 5, wm = wid >> 2, wn = wid & 3;
    const float* bias_s = (const float*)(sm + OFF_BIAS);
    const int r0 = wm * 32 + (lane >> 2);
    const int c0 = wn * 64 + (lane & 3) * 2;
#pragma unroll
    for (int mt = 0; mt < 2; mt++)
#pragma unroll
    for (int nt = 0; nt < 8; nt++) {
        int col = c0 + nt * 8;
        float b0 = bias_s[col], b1 = bias_s[col + 1];
        float v0 = fmaxf(acc[mt][nt][0] + b0, 0.f);
        float v1 = fmaxf(acc[mt][nt][1] + b1, 0.f);
        float v2 = fmaxf(acc[mt][nt][2] + b0, 0.f);
        float v3 = fmaxf(acc[mt][nt][3] + b1, 0.f);
        __half2 p01 = __floats2half2_rn(v0, v1);
        __half2 p23 = __floats2half2_rn(v2, v3);
        int rowi = r0 + mt * 16;
        *(uint32_t*)(sm + OFF_A + rowi * A_STRIDE + col * 2) = *(uint32_t*)&p01;
        *(uint32_t*)(sm + OFF_A + (rowi + 8) * A_STRIDE + col * 2) = *(uint32_t*)&p23;
    }
    __syncthreads();
}

// prologue for the 96-row layer3 (pairs wn<3 own 32 rows each)
__device__ __forceinline__ void prologue96(uint32_t smb, const __half* __restrict__ w, int tid) {
    const int lane = tid & 31, wid = tid >> 5;
    const int wm = wid >> 2, wn = wid & 3;
    if (wn >= 3) return;
    const uint32_t pairbase = smb + OFF_B + (uint32_t)(wn * PAIR_RING);
    const int idx = wm * 32 + lane;          // 0..63
    const int row = idx >> 1, half = idx & 1;
    const uint32_t bdst = pairbase + (uint32_t)(row * B_STRIDE + half * 16);
    const __half* src = w + (wn*32 + row) * 256 + half * 8;
#pragma unroll
    for (int s = 0; s < 3; s++) {
        cp16(bdst + s * BSTG, src + s * 16);
        CP_COMMIT();
    }
}

// 64x96x256 layer mainloop (reg layer3, N padded to 96).
__device__ __forceinline__ void gemm96(char* sm, uint32_t smb,
    const __half* __restrict__ w, float acc[2][4][4], int tid)
{
    const int lane = tid & 31, wid = tid >> 5;
    const int wm = wid >> 2, wn = wid & 3;
    if (wn >= 3) { __syncthreads(); return; }
    const int a_row  = (lane & 7) + ((lane >> 3) & 1) * 8;
    const int a_koff = (lane >> 4) * 8;
    const int b_n    = (lane & 7) + ((lane >> 4) << 3);
    const int b_koff = ((lane >> 3) & 1) * 8;
    const int barid  = 1 + wn;

    const uint32_t aB = smb + OFF_A + (uint32_t)((wm*32 + a_row) * A_STRIDE + a_koff * 2);
    const uint32_t pairbase = smb + OFF_B + (uint32_t)(wn * PAIR_RING);
    const uint32_t bOff = (uint32_t)(b_n * B_STRIDE + b_koff * 2);

    const int idx = wm * 32 + lane;          // 0..63
    const int row = idx >> 1, half = idx & 1;
    const uint32_t bdst = pairbase + (uint32_t)(row * B_STRIDE + half * 16);
    const __half* src = w + (wn*32 + row) * 256 + half * 8;

    for (int ks = 0; ks < 16; ks++) {
        uint32_t ah0[4], ah1[4];
        ldsm4(ah0, aB + (uint32_t)(ks * 32));
        ldsm4(ah1, aB + (uint32_t)(16 * A_STRIDE + ks * 32));

        CP_WAIT2();
        bar_pair(barid);
        if (ks + 3 < 16)
            cp16(bdst + (uint32_t)(((ks + 3) & 3) * BSTG), src + (ks + 3) * 16);
        CP_COMMIT();

        const uint32_t bb = pairbase + (uint32_t)((ks & 3) * BSTG) + bOff;
        uint32_t bh[4][2];
#pragma unroll
        for (int p = 0; p < 2; p++) {
            uint32_t r[4];
            ldsm4(r, bb + p * (16 * B_STRIDE));
            bh[2*p][0]=r[0]; bh[2*p][1]=r[1]; bh[2*p+1][0]=r[2]; bh[2*p+1][1]=r[3];
        }
#pragma unroll
        for (int nt = 0; nt < 4; nt++) mmaf16(acc[0][nt], ah0, bh[nt]);
#pragma unroll
        for (int nt = 0; nt < 4; nt++) mmaf16(acc[1][nt], ah1, bh[nt]);
    }
    __syncthreads();
}

// ---------------- main kernel ----------------
__global__ void __launch_bounds__(THREADS, 2) gfocal_mma_kernel(
    const float* __restrict__ x,
    const float* __restrict__ cb1, const float* __restrict__ cb2,
    const float* __restrict__ cw3, const float* __restrict__ cb3,
    const float* __restrict__ rb1, const float* __restrict__ rb2,
    const float* __restrict__ rb3,
    const float* __restrict__ qw1, const float* __restrict__ qb1,
    const float* __restrict__ qw2, const float* __restrict__ qb2,
    float* __restrict__ cls_out, float* __restrict__ box_out,
    float* __restrict__ reg_out)
{
    extern __shared__ char sm[];
    const uint32_t smb = smem_u32(sm);
    const int tid  = threadIdx.x;
    const int base = blockIdx.x * BM;

    float* bias_s = (float*)(sm + OFF_BIAS);
    float* stat_s = (float*)(sm + OFF_STAT);
    float* stage  = (float*)(sm + OFF_STAGE);
    float* qw1_s  = (float*)(sm + OFF_QW1);
    float* p1_s   = (float*)(sm + OFF_P1);
    float* p2_s   = (float*)(sm + OFF_P2);

    float acc[2][8][4];

    // ================= REG branch =================
    prologue256(smb, g_wh[0], tid);            // overlaps x load
    if (tid < 256) bias_s[tid] = rb1[tid];
    load_x_h(sm, x + (size_t)base * 256, tid);
    __syncthreads();
#pragma unroll
    for (int i = 0; i < 64; i++) ((float*)acc)[i] = 0.f;
    gemm256(sm, smb, g_wh[0], acc, tid);
    prologue256(smb, g_wh[1], tid);            // overlaps epilogue
    epi256(sm, acc, tid);

    if (tid < 256) bias_s[tid] = rb2[tid];
#pragma unroll
    for (int i = 0; i < 64; i++) ((float*)acc)[i] = 0.f;
    gemm256(sm, smb, g_wh[1], acc, tid);
    prologue96(smb, g_w3h, tid);               // overlaps epilogue
    epi256(sm, acc, tid);

    if (tid < 68) bias_s[tid] = rb3[tid];
    __syncthreads();
    {
        float acc3[2][4][4];
#pragma unroll
        for (int i = 0; i < 32; i++) ((float*)acc3)[i] = 0.f;
        gemm96(sm, smb, g_w3h, acc3, tid);
        const int lane = tid & 31, wid = tid >> 5;
        const int wm = wid >> 2, wn = wid & 3;
        if (wn < 3) {
            const int r0 = wm * 32 + (lane >> 2);
            const int cb = (lane & 3) * 2;
#pragma unroll
            for (int mt = 0; mt < 2; mt++)
#pragma unroll
            for (int nt = 0; nt < 4; nt++) {
                int col = wn * 32 + nt * 8 + cb;
                if (col < 68) {
                    int r = r0 + mt * 16;
                    float b0 = bias_s[col], b1 = bias_s[col + 1];
                    stage[r * 76 + col]       = acc3[mt][nt][0] + b0;
                    stage[r * 76 + col + 1]   = acc3[mt][nt][1] + b1;
                    stage[(r+8) * 76 + col]   = acc3[mt][nt][2] + b0;
                    stage[(r+8) * 76 + col+1] = acc3[mt][nt][3] + b1;
                }
            }
        }
    }
    __syncthreads();

    // per-(token,side) epilogue: softmax / integral / top4 stats — 256-way
    {
        const int m = tid >> 2, g = tid & 3;
        float lg[17];
#pragma unroll
        for (int j = 0; j < 17; j++) lg[j] = stage[m * 76 + g * 17 + j];
        float mx = lg[0];
#pragma unroll
        for (int j = 1; j < 17; j++) mx = fmaxf(mx, lg[j]);
        float e[17], s = 0.f, si = 0.f;
#pragma unroll
        for (int j = 0; j < 17; j++) {
            e[j] = __expf(lg[j] - mx);
            s += e[j]; si += e[j] * (float)j;
        }
        box_out[(size_t)(base + m) * 4 + g] = si / (s * 16.0f);
        float inv = 1.0f / s, tsum = 0.f;
#pragma unroll
        for (int t4 = 0; t4 < 4; t4++) {
            float mv = -1.0f; int mi = 0;
#pragma unroll
            for (int j = 0; j < 17; j++)
                if (e[j] > mv) { mv = e[j]; mi = j; }
            float tv = mv * inv;
            stat_s[m * 20 + g * 5 + t4] = tv;
            tsum += tv;
            e[mi] = -1.0f;
        }
        stat_s[m * 20 + g * 5 + 4] = tsum * 0.25f;
    }
    for (int idx = tid; idx < 64 * 68; idx += THREADS) {
        int row = idx / 68;
        int col = idx - row * 68;
        reg_out[(size_t)base * 68 + idx] = stage[row * 76 + col];
    }
    __syncthreads();   // stage (aliases B region) fully read before CLS prologue

    // ================= CLS branch =================
    prologue256(smb, g_wh[2], tid);            // overlaps x reload
    if (tid < 256) bias_s[tid] = cb1[tid];
    load_x_h(sm, x + (size_t)base * 256, tid);
    __syncthreads();
#pragma unroll
    for (int i = 0; i < 64; i++) ((float*)acc)[i] = 0.f;
    gemm256(sm, smb, g_wh[2], acc, tid);
    prologue256(smb, g_wh[3], tid);            // overlaps epilogue
    epi256(sm, acc, tid);

    if (tid < 256) bias_s[tid] = cb2[tid];
#pragma unroll
    for (int i = 0; i < 64; i++) ((float*)acc)[i] = 0.f;
    gemm256(sm, smb, g_wh[3], acc, tid);
    epi256(sm, acc, tid);

    // cls layer3 partials (4-way K split) + qw1 smem load
    {
        const int m = tid & 63, qtr = tid >> 6;
        const char* pa = sm + OFF_A + m * A_STRIDE;
        float p = 0.0f;
        const int k_begin = qtr * 64;
        for (int k0 = k_begin; k0 < k_begin + 64; k0 += 8) {
            uint4 uh = *(const uint4*)(pa + k0 * 2);
            float4 w0 = *(const float4*)(cw3 + k0);
            float4 w1 = *(const float4*)(cw3 + k0 + 4);
            const __half2* ph = (const __half2*)&uh;
            float wv[8] = {w0.x,w0.y,w0.z,w0.w,w1.x,w1.y,w1.z,w1.w};
#pragma unroll
            for (int e2 = 0; e2 < 4; e2++) {
                float2 hv = __half22float2(ph[e2]);
                p = fmaf(hv.x, wv[e2*2],   p);
                p = fmaf(hv.y, wv[e2*2+1], p);
            }
        }
        p1_s[tid] = p;
    }
    for (int idx = tid; idx < 64 * 20; idx += THREADS) qw1_s[idx] = qw1[idx];
    __syncthreads();

    // quality head partials (4-way O split)
    {
        const int m = tid & 63, ch = tid >> 6;
        const float* st = stat_s + m * 20;
        float qp = 0.0f;
        for (int o = ch * 16; o < ch * 16 + 16; o++) {
            float hsum = qb1[o];
#pragma unroll
            for (int c = 0; c < 20; c++)
                hsum = fmaf(qw1_s[o * 20 + c], st[c], hsum);
            qp = fmaf(fmaxf(hsum, 0.0f), qw2[o], qp);
        }
        p2_s[tid] = qp;
    }
    __syncthreads();

    if (tid < 64) {
        float sacc = cb3[0] + p1_s[tid] + p1_s[tid+64] + p1_s[tid+128] + p1_s[tid+192];
        float q    = qb2[0] + p2_s[tid] + p2_s[tid+64] + p2_s[tid+128] + p2_s[tid+192];
        cls_out[base + tid] = sigmoidf_(sacc) * sigmoidf_(q);
    }
}

extern "C" void kernel_launch(void* const* d_in, const int* in_sizes, int n_in,
                              void* d_out, int out_size)
{
    const float* x   = (const float*)d_in[0];
    const float* cw1 = (const float*)d_in[1];
    const float* cb1 = (const float*)d_in[2];
    const float* cw2 = (const float*)d_in[3];
    const float* cb2 = (const float*)d_in[4];
    const float* cw3 = (const float*)d_in[5];
    const float* cb3 = (const float*)d_in[6];
    const float* rw1 = (const float*)d_in[7];
    const float* rb1 = (const float*)d_in[8];
    const float* rw2 = (const float*)d_in[9];
    const float* rb2 = (const float*)d_in[10];
    const float* rw3 = (const float*)d_in[11];
    const float* rb3 = (const float*)d_in[12];
    const float* qw1 = (const float*)d_in[13];
    const float* qb1 = (const float*)d_in[14];
    const float* qw2 = (const float*)d_in[15];
    const float* qb2 = (const float*)d_in[16];

    float* out = (float*)d_out;
    float* cls_out = out;
    float* box_out = out + NTOK;
    float* reg_out = out + NTOK + (size_t)NTOK * 4;

    prep_kernel<<<256, 256>>>(rw1, rw2, cw1, cw2, rw3);

    cudaFuncSetAttribute(gfocal_mma_kernel,
                         cudaFuncAttributeMaxDynamicSharedMemorySize, SMEM_BYTES);
    gfocal_mma_kernel<<<NBLK, THREADS, SMEM_BYTES>>>(
        x, cb1, cb2, cw3, cb3, rb1, rb2, rb3,
        qw1, qb1, qw2, qb2,
        cls_out, box_out, reg_out);
}

// round 13
// speedup vs baseline: 1.3162x; 1.0547x over previous
#include <cuda_runtime.h>
#include <cuda_fp16.h>
#include <stdint.h>

#define NTOK    294912
#define TILES   4608            // NTOK/64
#define TPC     4               // tiles per CTA
#define NCTA    (TILES / TPC)   // 1152
#define THREADS 256

// ---- smem byte offsets ----
#define OFF_W    0              // 256 x 528 = 135168 (resident layer weights)
#define OFF_A0   135168         // 64 x 528 fp16 tile buf
#define OFF_A1   168960
#define OFF_BIAS 202752         // 256 f32
#define OFF_STAT 203776         // 4 tiles x 64 x 20 f32 = 20480
#define OFF_QW1  224256         // 64*20 f32 = 5120
#define OFF_P1   229376         // 256 f32
#define OFF_P2   230400         // 256 f32
#define SMEM_BYTES 231424

#define STRIDE 528

// ---- device scratch ----
__device__ __half g_xh[75497472];    // x in fp16
__device__ __half g_h1[75497472];    // activation scratch A
__device__ __half g_h2[75497472];    // activation scratch B
__device__ __half g_wh[4][65536];    // 0=rw1 1=rw2 2=cw1 3=cw2
__device__ __half g_w3h[128 * 256];  // rw3 padded to 128 rows

// ---------------- helpers ----------------
__device__ __forceinline__ uint32_t smem_u32(const void* p) {
    uint32_t a;
    asm("{ .reg .u64 t; cvta.to.shared.u64 t, %1; cvt.u32.u64 %0, t; }"
        : "=r"(a) : "l"(p));
    return a;
}
__device__ __forceinline__ void ldsm4(uint32_t* r, uint32_t addr) {
    asm volatile("ldmatrix.sync.aligned.m8n8.x4.shared.b16 {%0,%1,%2,%3}, [%4];"
        : "=r"(r[0]), "=r"(r[1]), "=r"(r[2]), "=r"(r[3]) : "r"(addr));
}
__device__ __forceinline__ void mmaf16(float* c, const uint32_t* a, const uint32_t* b) {
    asm volatile("mma.sync.aligned.m16n8k16.row.col.f32.f16.f16.f32 "
        "{%0,%1,%2,%3}, {%4,%5,%6,%7}, {%8,%9}, {%0,%1,%2,%3};"
        : "+f"(c[0]), "+f"(c[1]), "+f"(c[2]), "+f"(c[3])
        : "r"(a[0]), "r"(a[1]), "r"(a[2]), "r"(a[3]), "r"(b[0]), "r"(b[1]));
}
__device__ __forceinline__ void cp16(uint32_t dst, const void* src) {
    asm volatile("cp.async.cg.shared.global [%0], [%1], 16;" :: "r"(dst), "l"(src));
}
#define CP_COMMIT() asm volatile("cp.async.commit_group;" ::: "memory")
#define CP_WAIT1()  asm volatile("cp.async.wait_group 1;" ::: "memory")
__device__ __forceinline__ void bar_g(int id) {
    asm volatile("bar.sync %0, 128;" :: "r"(id) : "memory");
}
__device__ __forceinline__ float sigmoidf_(float v) { return 1.0f / (1.0f + __expf(-v)); }

// ---------------- prep kernel: x + weights -> fp16 ----------------
__global__ void prep_kernel(const float* __restrict__ x,
                            const float* rw1, const float* rw2,
                            const float* cw1, const float* cw2,
                            const float* rw3) {
    int bid = blockIdx.x, tid = threadIdx.x;
    if (bid < 18432) {
        size_t base = ((size_t)bid * 256 + tid) * 16;
        const float4* xs = (const float4*)(x + base);
        uint4* dst = (uint4*)(g_xh + base);
#pragma unroll
        for (int i = 0; i < 2; i++) {
            float4 a = xs[i * 2], b = xs[i * 2 + 1];
            __half2 h0 = __floats2half2_rn(a.x, a.y), h1 = __floats2half2_rn(a.z, a.w);
            __half2 h2 = __floats2half2_rn(b.x, b.y), h3 = __floats2half2_rn(b.z, b.w);
            uint4 v;
            v.x = *(uint32_t*)&h0; v.y = *(uint32_t*)&h1;
            v.z = *(uint32_t*)&h2; v.w = *(uint32_t*)&h3;
            dst[i] = v;
        }
    } else {
        int i = (bid - 18432) * 256 + tid;
        g_wh[0][i] = __float2half_rn(rw1[i]);
        g_wh[1][i] = __float2half_rn(rw2[i]);
        g_wh[2][i] = __float2half_rn(cw1[i]);
        g_wh[3][i] = __float2half_rn(cw2[i]);
        if (i < 128 * 256) {
            int row = i >> 8;
            g_w3h[i] = __float2half_rn((row < 68) ? rw3[i] : 0.0f);
        }
    }
}

// ---------------- load helpers (one commit each) ----------------
__device__ __forceinline__ void ld_W(uint32_t smb, const __half* __restrict__ w,
                                     int rows, int tid) {
    int n = rows * 32;
    for (int idx = tid; idx < n; idx += THREADS) {
        int row = idx >> 5, seg = idx & 31;
        cp16(smb + OFF_W + row * STRIDE + seg * 16, w + row * 256 + seg * 8);
    }
    CP_COMMIT();
}
__device__ __forceinline__ void ld_tile(uint32_t smb, uint32_t off,
                                        const __half* __restrict__ src, int tid) {
    for (int idx = tid; idx < 2048; idx += THREADS) {
        int row = idx >> 5, seg = idx & 31;
        cp16(smb + off + row * STRIDE + seg * 16, src + row * 256 + seg * 8);
    }
    CP_COMMIT();
}

// ---------------- gemms (W resident in smem, no barriers inside) ----------------
__device__ __forceinline__ void gemm256W(uint32_t smb, uint32_t aoff,
                                         float acc[2][8][4], int tid) {
    const int lane = tid & 31, wid = tid >> 5;
    const int wm = wid >> 2, wn = wid & 3;
    const int a_row  = (lane & 7) + ((lane >> 3) & 1) * 8;
    const int a_koff = (lane >> 4) * 8;
    const int b_n    = (lane & 7) + ((lane >> 4) << 3);
    const int b_koff = ((lane >> 3) & 1) * 8;
    const uint32_t aB = smb + aoff + (uint32_t)((wm * 32 + a_row) * STRIDE + a_koff * 2);
    const uint32_t bB = smb + OFF_W + (uint32_t)((wn * 64 + b_n) * STRIDE + b_koff * 2);
#pragma unroll 4
    for (int ks = 0; ks < 16; ks++) {
        uint32_t ah0[4], ah1[4];
        ldsm4(ah0, aB + (uint32_t)(ks * 32));
        ldsm4(ah1, aB + (uint32_t)(16 * STRIDE + ks * 32));
        uint32_t bh[8][2];
#pragma unroll
        for (int p = 0; p < 4; p++) {
            uint32_t r[4];
            ldsm4(r, bB + (uint32_t)(p * 16 * STRIDE + ks * 32));
            bh[2*p][0]=r[0]; bh[2*p][1]=r[1]; bh[2*p+1][0]=r[2]; bh[2*p+1][1]=r[3];
        }
#pragma unroll
        for (int nt = 0; nt < 8; nt++) mmaf16(acc[0][nt], ah0, bh[nt]);
#pragma unroll
        for (int nt = 0; nt < 8; nt++) mmaf16(acc[1][nt], ah1, bh[nt]);
    }
}

__device__ __forceinline__ void gemm128W(uint32_t smb, uint32_t aoff,
                                         float acc[2][4][4], int tid) {
    const int lane = tid & 31, wid = tid >> 5;
    const int wm = wid >> 2, wn = wid & 3;
    const int a_row  = (lane & 7) + ((lane >> 3) & 1) * 8;
    const int a_koff = (lane >> 4) * 8;
    const int b_n    = (lane & 7) + ((lane >> 4) << 3);
    const int b_koff = ((lane >> 3) & 1) * 8;
    const uint32_t aB = smb + aoff + (uint32_t)((wm * 32 + a_row) * STRIDE + a_koff * 2);
    const uint32_t bB = smb + OFF_W + (uint32_t)((wn * 32 + b_n) * STRIDE + b_koff * 2);
#pragma unroll 4
    for (int ks = 0; ks < 16; ks++) {
        uint32_t ah0[4], ah1[4];
        ldsm4(ah0, aB + (uint32_t)(ks * 32));
        ldsm4(ah1, aB + (uint32_t)(16 * STRIDE + ks * 32));
        uint32_t bh[4][2];
#pragma unroll
        for (int p = 0; p < 2; p++) {
            uint32_t r[4];
            ldsm4(r, bB + (uint32_t)(p * 16 * STRIDE + ks * 32));
            bh[2*p][0]=r[0]; bh[2*p][1]=r[1]; bh[2*p+1][0]=r[2]; bh[2*p+1][1]=r[3];
        }
#pragma unroll
        for (int nt = 0; nt < 4; nt++) mmaf16(acc[0][nt], ah0, bh[nt]);
#pragma unroll
        for (int nt = 0; nt < 4; nt++) mmaf16(acc[1][nt], ah1, bh[nt]);
    }
}

// ---------------- epilogues ----------------
// bias+relu -> fp16 into A buf (STS), then coalesced STG to scratch
__device__ __forceinline__ void epi_h(char* sm, uint32_t bufoff, float acc[2][8][4],
                                      __half* __restrict__ dst, int tid) {
    const int lane = tid & 31, wid = tid >> 5, wm = wid >> 2, wn = wid & 3;
    const float* bias_s = (const float*)(sm + OFF_BIAS);
    bar_g(1 + wm);                         // same-wm warps done reading A rows
    const int r0 = wm * 32 + (lane >> 2);
    const int c0 = wn * 64 + (lane & 3) * 2;
#pragma unroll
    for (int mt = 0; mt < 2; mt++)
#pragma unroll
    for (int nt = 0; nt < 8; nt++) {
        int col = c0 + nt * 8;
        float b0 = bias_s[col], b1 = bias_s[col + 1];
        float v0 = fmaxf(acc[mt][nt][0] + b0, 0.f);
        float v1 = fmaxf(acc[mt][nt][1] + b1, 0.f);
        float v2 = fmaxf(acc[mt][nt][2] + b0, 0.f);
        float v3 = fmaxf(acc[mt][nt][3] + b1, 0.f);
        __half2 p01 = __floats2half2_rn(v0, v1);
        __half2 p23 = __floats2half2_rn(v2, v3);
        int row = r0 + mt * 16;
        *(uint32_t*)(sm + bufoff + row * STRIDE + col * 2) = *(uint32_t*)&p01;
        *(uint32_t*)(sm + bufoff + (row + 8) * STRIDE + col * 2) = *(uint32_t*)&p23;
    }
    __syncthreads();
    for (int idx = tid; idx < 2048; idx += THREADS) {
        int row = idx >> 5, seg = idx & 31;
        uint4 v = *(const uint4*)(sm + bufoff + row * STRIDE + seg * 16);
        *(uint4*)(dst + row * 256 + seg * 8) = v;
    }
}

// layer3 epilogue: logits -> stage(f32 in buf), softmax/top4/integral
__device__ __forceinline__ void epi_softmax(char* sm, uint32_t bufoff, float acc3[2][4][4],
                                            int tileg, int t,
                                            float* __restrict__ box_out,
                                            float* __restrict__ reg_out, int tid) {
    const int lane = tid & 31, wid = tid >> 5, wm = wid >> 2, wn = wid & 3;
    const float* bias_s = (const float*)(sm + OFF_BIAS);
    float* stage = (float*)(sm + bufoff);
    float* stat_s = (float*)(sm + OFF_STAT) + t * 1280;
    bar_g(1 + wm);
    const int r0 = wm * 32 + (lane >> 2);
    const int cb = (lane & 3) * 2;
#pragma unroll
    for (int mt = 0; mt < 2; mt++)
#pragma unroll
    for (int nt = 0; nt < 4; nt++) {
        int col = wn * 32 + nt * 8 + cb;
        if (col < 68) {
            int r = r0 + mt * 16;
            float b0 = bias_s[col], b1 = bias_s[col + 1];
            stage[r * 76 + col]         = acc3[mt][nt][0] + b0;
            stage[r * 76 + col + 1]     = acc3[mt][nt][1] + b1;
            stage[(r + 8) * 76 + col]   = acc3[mt][nt][2] + b0;
            stage[(r + 8) * 76 + col+1] = acc3[mt][nt][3] + b1;
        }
    }
    __syncthreads();
    {
        const int m = tid >> 2, g = tid & 3;
        float lg[17];
#pragma unroll
        for (int j = 0; j < 17; j++) lg[j] = stage[m * 76 + g * 17 + j];
        float mx = lg[0];
#pragma unroll
        for (int j = 1; j < 17; j++) mx = fmaxf(mx, lg[j]);
        float e[17], s = 0.f, si = 0.f;
#pragma unroll
        for (int j = 0; j < 17; j++) {
            e[j] = __expf(lg[j] - mx);
            s += e[j]; si += e[j] * (float)j;
        }
        box_out[(size_t)(tileg * 64 + m) * 4 + g] = si / (s * 16.0f);
        float inv = 1.0f / s, tsum = 0.f;
#pragma unroll
        for (int t4 = 0; t4 < 4; t4++) {
            float mv = -1.0f; int mi = 0;
#pragma unroll
            for (int j = 0; j < 17; j++)
                if (e[j] > mv) { mv = e[j]; mi = j; }
            float tv = mv * inv;
            stat_s[m * 20 + g * 5 + t4] = tv;
            tsum += tv;
            e[mi] = -1.0f;
        }
        stat_s[m * 20 + g * 5 + 4] = tsum * 0.25f;
    }
    float* ro = reg_out + (size_t)tileg * 4352;
    for (int idx = tid; idx < 64 * 68; idx += THREADS) {
        int row = idx / 68;
        int col = idx - row * 68;
        ro[idx] = stage[row * 76 + col];
    }
}

// final cls epilogue: h2->smem, cls layer3 + quality head, write cls_out
__device__ __forceinline__ void epi_cls(char* sm, uint32_t bufoff, float acc[2][8][4],
    int tileg, int t,
    const float* __restrict__ cw3, const float* __restrict__ cb3,
    const float* __restrict__ qb1, const float* __restrict__ qw2,
    const float* __restrict__ qb2, float* __restrict__ cls_out, int tid) {
    const int lane = tid & 31, wid = tid >> 5, wm = wid >> 2, wn = wid & 3;
    const float* bias_s = (const float*)(sm + OFF_BIAS);
    float* qw1_s = (float*)(sm + OFF_QW1);
    float* p1_s  = (float*)(sm + OFF_P1);
    float* p2_s  = (float*)(sm + OFF_P2);
    bar_g(1 + wm);
    const int r0 = wm * 32 + (lane >> 2);
    const int c0 = wn * 64 + (lane & 3) * 2;
#pragma unroll
    for (int mt = 0; mt < 2; mt++)
#pragma unroll
    for (int nt = 0; nt < 8; nt++) {
        int col = c0 + nt * 8;
        float b0 = bias_s[col], b1 = bias_s[col + 1];
        float v0 = fmaxf(acc[mt][nt][0] + b0, 0.f);
        float v1 = fmaxf(acc[mt][nt][1] + b1, 0.f);
        float v2 = fmaxf(acc[mt][nt][2] + b0, 0.f);
        float v3 = fmaxf(acc[mt][nt][3] + b1, 0.f);
        __half2 p01 = __floats2half2_rn(v0, v1);
        __half2 p23 = __floats2half2_rn(v2, v3);
        int row = r0 + mt * 16;
        *(uint32_t*)(sm + bufoff + row * STRIDE + col * 2) = *(uint32_t*)&p01;
        *(uint32_t*)(sm + bufoff + (row + 8) * STRIDE + col * 2) = *(uint32_t*)&p23;
    }
    __syncthreads();
    // cls layer3 partials (4-way K split)
    {
        const int m = tid & 63, qtr = tid >> 6;
        const char* pa = sm + bufoff + m * STRIDE;
        float p = 0.0f;
        const int kb = qtr * 64;
        for (int k0 = kb; k0 < kb + 64; k0 += 8) {
            uint4 uh = *(const uint4*)(pa + k0 * 2);
            float4 w0 = *(const float4*)(cw3 + k0);
            float4 w1 = *(const float4*)(cw3 + k0 + 4);
            const __half2* ph = (const __half2*)&uh;
            float wv[8] = {w0.x,w0.y,w0.z,w0.w,w1.x,w1.y,w1.z,w1.w};
#pragma unroll
            for (int e2 = 0; e2 < 4; e2++) {
                float2 hv = __half22float2(ph[e2]);
                p = fmaf(hv.x, wv[e2*2],   p);
                p = fmaf(hv.y, wv[e2*2+1], p);
            }
        }
        p1_s[tid] = p;
    }
    __syncthreads();
    // quality partials (4-way O split)
    {
        const int m = tid & 63, ch = tid >> 6;
        const float* st = (const float*)(sm + OFF_STAT) + t * 1280 + m * 20;
        float qp = 0.0f;
        for (int o = ch * 16; o < ch * 16 + 16; o++) {
            float hsum = qb1[o];
#pragma unroll
            for (int c = 0; c < 20; c++)
                hsum = fmaf(qw1_s[o * 20 + c], st[c], hsum);
            qp = fmaf(fmaxf(hsum, 0.0f), qw2[o], qp);
        }
        p2_s[tid] = qp;
    }
    __syncthreads();
    if (tid < 64) {
        float sacc = cb3[0] + p1_s[tid] + p1_s[tid+64] + p1_s[tid+128] + p1_s[tid+192];
        float q    = qb2[0] + p2_s[tid] + p2_s[tid+64] + p2_s[tid+128] + p2_s[tid+192];
        cls_out[tileg * 64 + tid] = sigmoidf_(sacc) * sigmoidf_(q);
    }
}

// ---------------- phase driver ----------------
// MODE: 0 = hidden layer (epi_h), 1 = reg layer3 (epi_softmax), 2 = cls final (epi_cls)
// NOTE: next-phase W is loaded AFTER the tile loop (all W reads retired via the
// epilogue's __syncthreads) — loading it inside the loop races with the t=3 GEMM.
template<int MODE>
__device__ __forceinline__ void run_phase(char* sm, uint32_t smb, int tid, int tile0,
    const __half* __restrict__ src, __half* __restrict__ dst,
    const float* __restrict__ bias,
    const __half* __restrict__ nextW, int nextWrows,
    const __half* __restrict__ nextsrc,
    const float* cw3, const float* cb3,
    const float* qb1, const float* qw2, const float* qb2,
    float* box_out, float* reg_out, float* cls_out) {
    float* bias_s = (float*)(sm + OFF_BIAS);
    for (int t = 0; t < TPC; t++) {
        __syncthreads();                                   // protect A bufs + bias
        if (t == 0) {
            if (MODE == 1) {
                if (tid < 128) bias_s[tid] = (tid < 68) ? bias[tid] : 0.0f;
            } else {
                if (tid < 256) bias_s[tid] = bias[tid];
            }
        }
        if (t < 3)
            ld_tile(smb, (t & 1) ? OFF_A0 : OFF_A1, src + (size_t)(t + 1) * 16384, tid);
        else
            CP_COMMIT();                                   // keep group cadence
        CP_WAIT1();
        __syncthreads();                                   // W + tile t ready
        const uint32_t bufoff = (t & 1) ? OFF_A1 : OFF_A0;
        if (MODE == 1) {
            float a3[2][4][4];
#pragma unroll
            for (int i = 0; i < 32; i++) ((float*)a3)[i] = 0.f;
            gemm128W(smb, bufoff, a3, tid);
            epi_softmax(sm, bufoff, a3, tile0 + t, t, box_out, reg_out, tid);
        } else {
            float a[2][8][4];
#pragma unroll
            for (int i = 0; i < 64; i++) ((float*)a)[i] = 0.f;
            gemm256W(smb, bufoff, a, tid);
            if (MODE == 0)
                epi_h(sm, bufoff, a, dst + (size_t)(tile0 + t) * 16384, tid);
            else
                epi_cls(sm, bufoff, a, tile0 + t, t, cw3, cb3, qb1, qw2, qb2, cls_out, tid);
        }
    }
    // safe: every thread passed the epilogue's __syncthreads, which is ordered
    // after all W reads of the last GEMM.
    if (nextW) ld_W(smb, nextW, nextWrows, tid);
    if (nextsrc) {
        __threadfence();       // our scratch STGs visible before re-read via cp.async
        ld_tile(smb, OFF_A0, nextsrc + (size_t)tile0 * 16384, tid);
    }
}

// ---------------- main kernel ----------------
__global__ void __launch_bounds__(THREADS, 1) gfocal_ws_kernel(
    const float* __restrict__ cb1, const float* __restrict__ cb2,
    const float* __restrict__ cw3, const float* __restrict__ cb3,
    const float* __restrict__ rb1, const float* __restrict__ rb2,
    const float* __restrict__ rb3,
    const float* __restrict__ qw1, const float* __restrict__ qb1,
    const float* __restrict__ qw2, const float* __restrict__ qb2,
    float* __restrict__ cls_out, float* __restrict__ box_out,
    float* __restrict__ reg_out) {
    extern __shared__ char sm[];
    const uint32_t smb = smem_u32(sm);
    const int tid = threadIdx.x;
    const int tile0 = blockIdx.x * TPC;

    float* qw1_s = (float*)(sm + OFF_QW1);
    for (int idx = tid; idx < 1280; idx += THREADS) qw1_s[idx] = qw1[idx];

    // prologue: W of phase 1 + tile0 of phase 1
    ld_W(smb, g_wh[0], 256, tid);
    ld_tile(smb, OFF_A0, g_xh + (size_t)tile0 * 16384, tid);

    // phase 1: reg layer1   x -> h1
    run_phase<0>(sm, smb, tid, tile0, g_xh + (size_t)tile0 * 16384, g_h1,
                 rb1, g_wh[1], 256, g_h1,
                 cw3, cb3, qb1, qw2, qb2, box_out, reg_out, cls_out);
    // phase 2: reg layer2   h1 -> h2
    run_phase<0>(sm, smb, tid, tile0, g_h1 + (size_t)tile0 * 16384, g_h2,
                 rb2, g_w3h, 128, g_h2,
                 cw3, cb3, qb1, qw2, qb2, box_out, reg_out, cls_out);
    // phase 3: reg layer3   h2 -> softmax/top4/box/reg_pred (stat into smem)
    run_phase<1>(sm, smb, tid, tile0, g_h2 + (size_t)tile0 * 16384, (/*unused*/ __half*)g_h1,
                 rb3, g_wh[2], 256, g_xh,
                 cw3, cb3, qb1, qw2, qb2, box_out, reg_out, cls_out);
    // phase 4: cls layer1   x -> h1
    run_phase<0>(sm, smb, tid, tile0, g_xh + (size_t)tile0 * 16384, g_h1,
                 cb1, g_wh[3], 256, g_h1,
                 cw3, cb3, qb1, qw2, qb2, box_out, reg_out, cls_out);
    // phase 5: cls layer2 + cls3 + quality -> cls_out
    run_phase<2>(sm, smb, tid, tile0, g_h1 + (size_t)tile0 * 16384, (/*unused*/ __half*)g_h2,
                 cb2, (const __half*)0, 0, (const __half*)0,
                 cw3, cb3, qb1, qw2, qb2, box_out, reg_out, cls_out);
}

extern "C" void kernel_launch(void* const* d_in, const int* in_sizes, int n_in,
                              void* d_out, int out_size) {
    const float* x   = (const float*)d_in[0];
    const float* cw1 = (const float*)d_in[1];
    const float* cb1 = (const float*)d_in[2];
    const float* cw2 = (const float*)d_in[3];
    const float* cb2 = (const float*)d_in[4];
    const float* cw3 = (const float*)d_in[5];
    const float* cb3 = (const float*)d_in[6];
    const float* rw1 = (const float*)d_in[7];
    const float* rb1 = (const float*)d_in[8];
    const float* rw2 = (const float*)d_in[9];
    const float* rb2 = (const float*)d_in[10];
    const float* rw3 = (const float*)d_in[11];
    const float* rb3 = (const float*)d_in[12];
    const float* qw1 = (const float*)d_in[13];
    const float* qb1 = (const float*)d_in[14];
    const float* qw2 = (const float*)d_in[15];
    const float* qb2 = (const float*)d_in[16];

    float* out = (float*)d_out;
    float* cls_out = out;
    float* box_out = out + NTOK;
    float* reg_out = out + NTOK + (size_t)NTOK * 4;

    prep_kernel<<<18688, 256>>>(x, rw1, rw2, cw1, cw2, rw3);

    cudaFuncSetAttribute(gfocal_ws_kernel,
                         cudaFuncAttributeMaxDynamicSharedMemorySize, SMEM_BYTES);
    gfocal_ws_kernel<<<NCTA, THREADS, SMEM_BYTES>>>(
        cb1, cb2, cw3, cb3, rb1, rb2, rb3,
        qw1, qb1, qw2, qb2,
        cls_out, box_out, reg_out);
}

// round 14
// speedup vs baseline: 1.3348x; 1.0141x over previous
#include <cuda_runtime.h>
#include <cuda_fp16.h>
#include <stdint.h>

#define NTOK    294912
#define TILES   4608            // NTOK/64
#define TPC     4               // tiles per CTA (2 pairs)
#define NCTA    (TILES / TPC)   // 1152
#define THREADS 256

// ---- smem byte offsets ----
#define OFF_W    0              // 256 x 528 = 135168 (resident layer weights)
#define OFF_A0   135168         // pair buffer: 128 x 528 fp16 (2 tiles)
#define TILE_B   33792          // 64*528
#define OFF_BIAS 202752         // 256 f32
#define OFF_STAT 203776         // 4 tiles x 64 x 20 f32 = 20480
#define OFF_QW1  224256         // 64*20 f32 = 5120
#define OFF_P1   229376         // 256 f32
#define OFF_P2   230400         // 256 f32
#define SMEM_BYTES 231424

#define STRIDE 528

// ---- device scratch ----
__device__ __half g_xh[75497472];    // x in fp16
__device__ __half g_h1[75497472];    // activation scratch A
__device__ __half g_h2[75497472];    // activation scratch B
__device__ __half g_wh[4][65536];    // 0=rw1 1=rw2 2=cw1 3=cw2
__device__ __half g_w3h[128 * 256];  // rw3 padded to 128 rows

// ---------------- helpers ----------------
__device__ __forceinline__ uint32_t smem_u32(const void* p) {
    uint32_t a;
    asm("{ .reg .u64 t; cvta.to.shared.u64 t, %1; cvt.u32.u64 %0, t; }"
        : "=r"(a) : "l"(p));
    return a;
}
__device__ __forceinline__ void ldsm4(uint32_t* r, uint32_t addr) {
    asm volatile("ldmatrix.sync.aligned.m8n8.x4.shared.b16 {%0,%1,%2,%3}, [%4];"
        : "=r"(r[0]), "=r"(r[1]), "=r"(r[2]), "=r"(r[3]) : "r"(addr));
}
__device__ __forceinline__ void mmaf16(float* c, const uint32_t* a, const uint32_t* b) {
    asm volatile("mma.sync.aligned.m16n8k16.row.col.f32.f16.f16.f32 "
        "{%0,%1,%2,%3}, {%4,%5,%6,%7}, {%8,%9}, {%0,%1,%2,%3};"
        : "+f"(c[0]), "+f"(c[1]), "+f"(c[2]), "+f"(c[3])
        : "r"(a[0]), "r"(a[1]), "r"(a[2]), "r"(a[3]), "r"(b[0]), "r"(b[1]));
}
__device__ __forceinline__ void cp16(uint32_t dst, const void* src) {
    asm volatile("cp.async.cg.shared.global [%0], [%1], 16;" :: "r"(dst), "l"(src));
}
#define CP_COMMIT() asm volatile("cp.async.commit_group;" ::: "memory")
#define CP_WAIT0()  asm volatile("cp.async.wait_group 0;" ::: "memory")
__device__ __forceinline__ void bar_g(int id) {
    asm volatile("bar.sync %0, 128;" :: "r"(id) : "memory");
}
__device__ __forceinline__ float sigmoidf_(float v) { return 1.0f / (1.0f + __expf(-v)); }

// ---------------- prep kernel: x + weights -> fp16 ----------------
__global__ void prep_kernel(const float* __restrict__ x,
                            const float* rw1, const float* rw2,
                            const float* cw1, const float* cw2,
                            const float* rw3) {
    int bid = blockIdx.x, tid = threadIdx.x;
    if (bid < 18432) {
        size_t base = ((size_t)bid * 256 + tid) * 16;
        const float4* xs = (const float4*)(x + base);
        uint4* dst = (uint4*)(g_xh + base);
#pragma unroll
        for (int i = 0; i < 2; i++) {
            float4 a = xs[i * 2], b = xs[i * 2 + 1];
            __half2 h0 = __floats2half2_rn(a.x, a.y), h1 = __floats2half2_rn(a.z, a.w);
            __half2 h2 = __floats2half2_rn(b.x, b.y), h3 = __floats2half2_rn(b.z, b.w);
            uint4 v;
            v.x = *(uint32_t*)&h0; v.y = *(uint32_t*)&h1;
            v.z = *(uint32_t*)&h2; v.w = *(uint32_t*)&h3;
            dst[i] = v;
        }
    } else {
        int i = (bid - 18432) * 256 + tid;
        g_wh[0][i] = __float2half_rn(rw1[i]);
        g_wh[1][i] = __float2half_rn(rw2[i]);
        g_wh[2][i] = __float2half_rn(cw1[i]);
        g_wh[3][i] = __float2half_rn(cw2[i]);
        if (i < 128 * 256) {
            int row = i >> 8;
            g_w3h[i] = __float2half_rn((row < 68) ? rw3[i] : 0.0f);
        }
    }
}

// ---------------- load helpers ----------------
__device__ __forceinline__ void ld_W(uint32_t smb, const __half* __restrict__ w,
                                     int rows, int tid) {
    int n = rows * 32;
    for (int idx = tid; idx < n; idx += THREADS) {
        int row = idx >> 5, seg = idx & 31;
        cp16(smb + OFF_W + row * STRIDE + seg * 16, w + row * 256 + seg * 8);
    }
    CP_COMMIT();
}
// load a PAIR of tiles (128 rows) into the A region
__device__ __forceinline__ void ld_pair(uint32_t smb, const __half* __restrict__ src, int tid) {
    for (int idx = tid; idx < 4096; idx += THREADS) {
        int row = idx >> 5, seg = idx & 31;
        cp16(smb + OFF_A0 + row * STRIDE + seg * 16, src + row * 256 + seg * 8);
    }
    CP_COMMIT();
}

// ---------------- pair GEMMs (W resident, both tiles per W sweep) ----------------
__device__ __forceinline__ void gemm256Wp(uint32_t smb, float acc[4][8][4], int tid) {
    const int lane = tid & 31, wid = tid >> 5;
    const int wm = wid >> 2, wn = wid & 3;
    const int a_row  = (lane & 7) + ((lane >> 3) & 1) * 8;
    const int a_koff = (lane >> 4) * 8;
    const int b_n    = (lane & 7) + ((lane >> 4) << 3);
    const int b_koff = ((lane >> 3) & 1) * 8;
    const uint32_t aB = smb + OFF_A0 + (uint32_t)((wm * 32 + a_row) * STRIDE + a_koff * 2);
    const uint32_t bB = smb + OFF_W + (uint32_t)((wn * 64 + b_n) * STRIDE + b_koff * 2);
#pragma unroll 2
    for (int ks = 0; ks < 16; ks++) {
        uint32_t ah[4][4];
        ldsm4(ah[0], aB + (uint32_t)(ks * 32));
        ldsm4(ah[1], aB + (uint32_t)(16 * STRIDE + ks * 32));
        ldsm4(ah[2], aB + (uint32_t)(TILE_B + ks * 32));
        ldsm4(ah[3], aB + (uint32_t)(TILE_B + 16 * STRIDE + ks * 32));
        uint32_t bh[8][2];
#pragma unroll
        for (int p = 0; p < 4; p++) {
            uint32_t r[4];
            ldsm4(r, bB + (uint32_t)(p * 16 * STRIDE + ks * 32));
            bh[2*p][0]=r[0]; bh[2*p][1]=r[1]; bh[2*p+1][0]=r[2]; bh[2*p+1][1]=r[3];
        }
#pragma unroll
        for (int f = 0; f < 4; f++)
#pragma unroll
            for (int nt = 0; nt < 8; nt++) mmaf16(acc[f][nt], ah[f], bh[nt]);
    }
}

__device__ __forceinline__ void gemm128Wp(uint32_t smb, float acc[4][4][4], int tid) {
    const int lane = tid & 31, wid = tid >> 5;
    const int wm = wid >> 2, wn = wid & 3;
    const int a_row  = (lane & 7) + ((lane >> 3) & 1) * 8;
    const int a_koff = (lane >> 4) * 8;
    const int b_n    = (lane & 7) + ((lane >> 4) << 3);
    const int b_koff = ((lane >> 3) & 1) * 8;
    const uint32_t aB = smb + OFF_A0 + (uint32_t)((wm * 32 + a_row) * STRIDE + a_koff * 2);
    const uint32_t bB = smb + OFF_W + (uint32_t)((wn * 32 + b_n) * STRIDE + b_koff * 2);
#pragma unroll 2
    for (int ks = 0; ks < 16; ks++) {
        uint32_t ah[4][4];
        ldsm4(ah[0], aB + (uint32_t)(ks * 32));
        ldsm4(ah[1], aB + (uint32_t)(16 * STRIDE + ks * 32));
        ldsm4(ah[2], aB + (uint32_t)(TILE_B + ks * 32));
        ldsm4(ah[3], aB + (uint32_t)(TILE_B + 16 * STRIDE + ks * 32));
        uint32_t bh[4][2];
#pragma unroll
        for (int p = 0; p < 2; p++) {
            uint32_t r[4];
            ldsm4(r, bB + (uint32_t)(p * 16 * STRIDE + ks * 32));
            bh[2*p][0]=r[0]; bh[2*p][1]=r[1]; bh[2*p+1][0]=r[2]; bh[2*p+1][1]=r[3];
        }
#pragma unroll
        for (int f = 0; f < 4; f++)
#pragma unroll
            for (int nt = 0; nt < 4; nt++) mmaf16(acc[f][nt], ah[f], bh[nt]);
    }
}

// ---------------- epilogues (pair versions) ----------------
// bias+relu -> fp16 into A pair buffer, then coalesced STG of both tiles
__device__ __forceinline__ void epi_h_pair(char* sm, float acc[4][8][4],
                                           __half* __restrict__ dst, int tid) {
    const int lane = tid & 31, wid = tid >> 5, wm = wid >> 2, wn = wid & 3;
    const float* bias_s = (const float*)(sm + OFF_BIAS);
    bar_g(1 + wm);                       // same-wm warps done reading these A rows
    const int r0 = wm * 32 + (lane >> 2);
    const int c0 = wn * 64 + (lane & 3) * 2;
#pragma unroll
    for (int f = 0; f < 4; f++) {
        const int tt = f >> 1, mt = f & 1;
        char* buf = sm + OFF_A0 + tt * TILE_B;
#pragma unroll
        for (int nt = 0; nt < 8; nt++) {
            int col = c0 + nt * 8;
            float b0 = bias_s[col], b1 = bias_s[col + 1];
            float v0 = fmaxf(acc[f][nt][0] + b0, 0.f);
            float v1 = fmaxf(acc[f][nt][1] + b1, 0.f);
            float v2 = fmaxf(acc[f][nt][2] + b0, 0.f);
            float v3 = fmaxf(acc[f][nt][3] + b1, 0.f);
            __half2 p01 = __floats2half2_rn(v0, v1);
            __half2 p23 = __floats2half2_rn(v2, v3);
            int row = r0 + mt * 16;
            *(uint32_t*)(buf + row * STRIDE + col * 2) = *(uint32_t*)&p01;
            *(uint32_t*)(buf + (row + 8) * STRIDE + col * 2) = *(uint32_t*)&p23;
        }
    }
    __syncthreads();
    for (int idx = tid; idx < 4096; idx += THREADS) {
        int row = idx >> 5, seg = idx & 31;
        uint4 v = *(const uint4*)(sm + OFF_A0 + row * STRIDE + seg * 16);
        *(uint4*)(dst + row * 256 + seg * 8) = v;
    }
}

// layer3 pair epilogue: logits -> f32 stages, softmax/top4/integral per tile
__device__ __forceinline__ void epi_softmax_pair(char* sm, float acc3[4][4][4],
                                                 int tp, int tileg0,
                                                 float* __restrict__ box_out,
                                                 float* __restrict__ reg_out, int tid) {
    const int lane = tid & 31, wid = tid >> 5, wm = wid >> 2, wn = wid & 3;
    const float* bias_s = (const float*)(sm + OFF_BIAS);
    bar_g(1 + wm);
    const int r0 = wm * 32 + (lane >> 2);
    const int cb = (lane & 3) * 2;
#pragma unroll
    for (int f = 0; f < 4; f++) {
        const int tt = f >> 1, mt = f & 1;
        float* stage = (float*)(sm + OFF_A0 + tt * TILE_B);
#pragma unroll
        for (int nt = 0; nt < 4; nt++) {
            int col = wn * 32 + nt * 8 + cb;
            if (col < 68) {
                int r = r0 + mt * 16;
                float b0 = bias_s[col], b1 = bias_s[col + 1];
                stage[r * 76 + col]         = acc3[f][nt][0] + b0;
                stage[r * 76 + col + 1]     = acc3[f][nt][1] + b1;
                stage[(r + 8) * 76 + col]   = acc3[f][nt][2] + b0;
                stage[(r + 8) * 76 + col+1] = acc3[f][nt][3] + b1;
            }
        }
    }
    __syncthreads();
#pragma unroll
    for (int tt = 0; tt < 2; tt++) {
        const float* stage = (const float*)(sm + OFF_A0 + tt * TILE_B);
        float* stat_s = (float*)(sm + OFF_STAT) + (2 * tp + tt) * 1280;
        const int m = tid >> 2, g = tid & 3;
        float lg[17];
#pragma unroll
        for (int j = 0; j < 17; j++) lg[j] = stage[m * 76 + g * 17 + j];
        float mx = lg[0];
#pragma unroll
        for (int j = 1; j < 17; j++) mx = fmaxf(mx, lg[j]);
        float e[17], s = 0.f, si = 0.f;
#pragma unroll
        for (int j = 0; j < 17; j++) {
            e[j] = __expf(lg[j] - mx);
            s += e[j]; si += e[j] * (float)j;
        }
        box_out[(size_t)((tileg0 + tt) * 64 + m) * 4 + g] = si / (s * 16.0f);
        float inv = 1.0f / s, tsum = 0.f;
#pragma unroll
        for (int t4 = 0; t4 < 4; t4++) {
            float mv = -1.0f; int mi = 0;
#pragma unroll
            for (int j = 0; j < 17; j++)
                if (e[j] > mv) { mv = e[j]; mi = j; }
            float tv = mv * inv;
            stat_s[m * 20 + g * 5 + t4] = tv;
            tsum += tv;
            e[mi] = -1.0f;
        }
        stat_s[m * 20 + g * 5 + 4] = tsum * 0.25f;
        float* ro = reg_out + (size_t)(tileg0 + tt) * 4352;
        for (int idx = tid; idx < 64 * 68; idx += THREADS) {
            int row = idx / 68;
            int col = idx - row * 68;
            ro[idx] = stage[row * 76 + col];
        }
    }
}

// final cls pair epilogue
__device__ __forceinline__ void epi_cls_pair(char* sm, float acc[4][8][4],
    int tp, int tileg0,
    const float* __restrict__ cw3, const float* __restrict__ cb3,
    const float* __restrict__ qb1, const float* __restrict__ qw2,
    const float* __restrict__ qb2, float* __restrict__ cls_out, int tid) {
    const int lane = tid & 31, wid = tid >> 5, wm = wid >> 2, wn = wid & 3;
    const float* bias_s = (const float*)(sm + OFF_BIAS);
    float* qw1_s = (float*)(sm + OFF_QW1);
    float* p1_s  = (float*)(sm + OFF_P1);
    float* p2_s  = (float*)(sm + OFF_P2);
    bar_g(1 + wm);
    const int r0 = wm * 32 + (lane >> 2);
    const int c0 = wn * 64 + (lane & 3) * 2;
#pragma unroll
    for (int f = 0; f < 4; f++) {
        const int tt = f >> 1, mt = f & 1;
        char* buf = sm + OFF_A0 + tt * TILE_B;
#pragma unroll
        for (int nt = 0; nt < 8; nt++) {
            int col = c0 + nt * 8;
            float b0 = bias_s[col], b1 = bias_s[col + 1];
            float v0 = fmaxf(acc[f][nt][0] + b0, 0.f);
            float v1 = fmaxf(acc[f][nt][1] + b1, 0.f);
            float v2 = fmaxf(acc[f][nt][2] + b0, 0.f);
            float v3 = fmaxf(acc[f][nt][3] + b1, 0.f);
            __half2 p01 = __floats2half2_rn(v0, v1);
            __half2 p23 = __floats2half2_rn(v2, v3);
            int row = r0 + mt * 16;
            *(uint32_t*)(buf + row * STRIDE + col * 2) = *(uint32_t*)&p01;
            *(uint32_t*)(buf + (row + 8) * STRIDE + col * 2) = *(uint32_t*)&p23;
        }
    }
    __syncthreads();
    for (int tt = 0; tt < 2; tt++) {
        // cls layer3 partials (4-way K split)
        {
            const int m = tid & 63, qtr = tid >> 6;
            const char* pa = sm + OFF_A0 + tt * TILE_B + m * STRIDE;
            float p = 0.0f;
            const int kb = qtr * 64;
            for (int k0 = kb; k0 < kb + 64; k0 += 8) {
                uint4 uh = *(const uint4*)(pa + k0 * 2);
                float4 w0 = *(const float4*)(cw3 + k0);
                float4 w1 = *(const float4*)(cw3 + k0 + 4);
                const __half2* ph = (const __half2*)&uh;
                float wv[8] = {w0.x,w0.y,w0.z,w0.w,w1.x,w1.y,w1.z,w1.w};
#pragma unroll
                for (int e2 = 0; e2 < 4; e2++) {
                    float2 hv = __half22float2(ph[e2]);
                    p = fmaf(hv.x, wv[e2*2],   p);
                    p = fmaf(hv.y, wv[e2*2+1], p);
                }
            }
            p1_s[tid] = p;
        }
        __syncthreads();
        // quality partials (4-way O split)
        {
            const int m = tid & 63, ch = tid >> 6;
            const float* st = (const float*)(sm + OFF_STAT) + (2 * tp + tt) * 1280 + m * 20;
            float qp = 0.0f;
            for (int o = ch * 16; o < ch * 16 + 16; o++) {
                float hsum = qb1[o];
#pragma unroll
                for (int c = 0; c < 20; c++)
                    hsum = fmaf(qw1_s[o * 20 + c], st[c], hsum);
                qp = fmaf(fmaxf(hsum, 0.0f), qw2[o], qp);
            }
            p2_s[tid] = qp;
        }
        __syncthreads();
        if (tid < 64) {
            float sacc = cb3[0] + p1_s[tid] + p1_s[tid+64] + p1_s[tid+128] + p1_s[tid+192];
            float q    = qb2[0] + p2_s[tid] + p2_s[tid+64] + p2_s[tid+128] + p2_s[tid+192];
            cls_out[(tileg0 + tt) * 64 + tid] = sigmoidf_(sacc) * sigmoidf_(q);
        }
        __syncthreads();   // p1_s/p2_s reusable for next tt
    }
}

// ---------------- phase driver ----------------
// MODE: 0 = hidden layer, 1 = reg layer3, 2 = cls final
// Entry condition: W for this phase + pair(0,1) already issued via cp.async.
template<int MODE>
__device__ __forceinline__ void run_phase(char* sm, uint32_t smb, int tid, int tile0,
    const __half* __restrict__ src, __half* __restrict__ dst,
    const float* __restrict__ bias,
    const __half* __restrict__ nextW, int nextWrows,
    const __half* __restrict__ nextsrc,
    const float* cw3, const float* cb3,
    const float* qb1, const float* qw2, const float* qb2,
    float* box_out, float* reg_out, float* cls_out) {
    float* bias_s = (float*)(sm + OFF_BIAS);
    for (int tp = 0; tp < 2; tp++) {
        if (tp == 0) {
            if (MODE == 1) {
                if (tid < 128) bias_s[tid] = (tid < 68) ? bias[tid] : 0.0f;
            } else {
                if (tid < 256) bias_s[tid] = bias[tid];
            }
        }
        CP_WAIT0();
        __syncthreads();                 // W + pair ready; bias visible
        if (MODE == 1) {
            float a3[4][4][4];
#pragma unroll
            for (int i = 0; i < 64; i++) ((float*)a3)[i] = 0.f;
            gemm128Wp(smb, a3, tid);
            epi_softmax_pair(sm, a3, tp, tile0 + 2 * tp, box_out, reg_out, tid);
        } else {
            float a[4][8][4];
#pragma unroll
            for (int i = 0; i < 128; i++) ((float*)a)[i] = 0.f;
            gemm256Wp(smb, a, tid);
            if (MODE == 0)
                epi_h_pair(sm, a, dst + (size_t)(tile0 + 2 * tp) * 16384, tid);
            else
                epi_cls_pair(sm, a, tp, tile0 + 2 * tp, cw3, cb3, qb1, qw2, qb2, cls_out, tid);
        }
        __syncthreads();                 // all buffer reads retired
        if (tp == 0)
            ld_pair(smb, src + (size_t)2 * 16384, tid);
    }
    // safe: post-epilogue __syncthreads ordered after all W reads
    if (nextW) ld_W(smb, nextW, nextWrows, tid);
    if (nextsrc) {
        __threadfence();                 // our scratch STGs visible to cp.async
        ld_pair(smb, nextsrc + (size_t)tile0 * 16384, tid);
    }
}

// ---------------- main kernel ----------------
__global__ void __launch_bounds__(THREADS, 1) gfocal_ws_kernel(
    const float* __restrict__ cb1, const float* __restrict__ cb2,
    const float* __restrict__ cw3, const float* __restrict__ cb3,
    const float* __restrict__ rb1, const float* __restrict__ rb2,
    const float* __restrict__ rb3,
    const float* __restrict__ qw1, const float* __restrict__ qb1,
    const float* __restrict__ qw2, const float* __restrict__ qb2,
    float* __restrict__ cls_out, float* __restrict__ box_out,
    float* __restrict__ reg_out) {
    extern __shared__ char sm[];
    const uint32_t smb = smem_u32(sm);
    const int tid = threadIdx.x;
    const int tile0 = blockIdx.x * TPC;

    float* qw1_s = (float*)(sm + OFF_QW1);
    for (int idx = tid; idx < 1280; idx += THREADS) qw1_s[idx] = qw1[idx];

    // prologue: W of phase 1 + first pair
    ld_W(smb, g_wh[0], 256, tid);
    ld_pair(smb, g_xh + (size_t)tile0 * 16384, tid);

    // phase 1: reg layer1   x -> h1
    run_phase<0>(sm, smb, tid, tile0, g_xh + (size_t)tile0 * 16384, g_h1,
                 rb1, g_wh[1], 256, g_h1,
                 cw3, cb3, qb1, qw2, qb2, box_out, reg_out, cls_out);
    // phase 2: reg layer2   h1 -> h2
    run_phase<0>(sm, smb, tid, tile0, g_h1 + (size_t)tile0 * 16384, g_h2,
                 rb2, g_w3h, 128, g_h2,
                 cw3, cb3, qb1, qw2, qb2, box_out, reg_out, cls_out);
    // phase 3: reg layer3   h2 -> softmax/top4/box/reg_pred
    run_phase<1>(sm, smb, tid, tile0, g_h2 + (size_t)tile0 * 16384, (/*unused*/ __half*)g_h1,
                 rb3, g_wh[2], 256, g_xh,
                 cw3, cb3, qb1, qw2, qb2, box_out, reg_out, cls_out);
    // phase 4: cls layer1   x -> h1
    run_phase<0>(sm, smb, tid, tile0, g_xh + (size_t)tile0 * 16384, g_h1,
                 cb1, g_wh[3], 256, g_h1,
                 cw3, cb3, qb1, qw2, qb2, box_out, reg_out, cls_out);
    // phase 5: cls layer2 + cls3 + quality -> cls_out
    run_phase<2>(sm, smb, tid, tile0, g_h1 + (size_t)tile0 * 16384, (/*unused*/ __half*)g_h2,
                 cb2, (const __half*)0, 0, (const __half*)0,
                 cw3, cb3, qb1, qw2, qb2, box_out, reg_out, cls_out);
}

extern "C" void kernel_launch(void* const* d_in, const int* in_sizes, int n_in,
                              void* d_out, int out_size) {
    const float* x   = (const float*)d_in[0];
    const float* cw1 = (const float*)d_in[1];
    const float* cb1 = (const float*)d_in[2];
    const float* cw2 = (const float*)d_in[3];
    const float* cb2 = (const float*)d_in[4];
    const float* cw3 = (const float*)d_in[5];
    const float* cb3 = (const float*)d_in[6];
    const float* rw1 = (const float*)d_in[7];
    const float* rb1 = (const float*)d_in[8];
    const float* rw2 = (const float*)d_in[9];
    const float* rb2 = (const float*)d_in[10];
    const float* rw3 = (const float*)d_in[11];
    const float* rb3 = (const float*)d_in[12];
    const float* qw1 = (const float*)d_in[13];
    const float* qb1 = (const float*)d_in[14];
    const float* qw2 = (const float*)d_in[15];
    const float* qb2 = (const float*)d_in[16];

    float* out = (float*)d_out;
    float* cls_out = out;
    float* box_out = out + NTOK;
    float* reg_out = out + NTOK + (size_t)NTOK * 4;

    prep_kernel<<<18688, 256>>>(x, rw1, rw2, cw1, cw2, rw3);

    cudaFuncSetAttribute(gfocal_ws_kernel,
                         cudaFuncAttributeMaxDynamicSharedMemorySize, SMEM_BYTES);
    gfocal_ws_kernel<<<NCTA, THREADS, SMEM_BYTES>>>(
        cb1, cb2, cw3, cb3, rb1, rb2, rb3,
        qw1, qb1, qw2, qb2,
        cls_out, box_out, reg_out);
}

// round 16
// speedup vs baseline: 1.3774x; 1.0319x over previous
#include <cuda_runtime.h>
#include <cuda_fp16.h>
#include <stdint.h>

#define NTOK    294912
#define TILES   4608            // NTOK/64
#define TPC     4               // tiles per CTA (2 pairs)
#define NCTA    (TILES / TPC)   // 1152
#define THREADS 512

// ---- smem byte offsets ----
#define OFF_W    0              // 256 x 528 = 135168 (resident layer weights)
#define OFF_A0   135168         // pair buffer: 128 x 528 fp16
#define OFF_BIAS 202752         // 256 f32
#define OFF_STAT 203776         // 4 tiles x 64 x 20 f32 = 20480
#define OFF_QW1  224256         // 64*20 f32 = 5120
#define OFF_P1   229376         // 256 f32 (cls3 partials)
#define OFF_P2   230400         // 256 f32 (quality partials)
#define SMEM_BYTES 231424

#define STRIDE 528

// ---- device scratch ----
__device__ __half g_xh[75497472];    // x in fp16
__device__ __half g_h1[75497472];    // activation scratch A
__device__ __half g_h2[75497472];    // activation scratch B
__device__ __half g_wh[4][65536];    // 0=rw1 1=rw2 2=cw1 3=cw2
__device__ __half g_w3h[128 * 256];  // rw3 padded to 128 rows

// ---------------- helpers ----------------
__device__ __forceinline__ uint32_t smem_u32(const void* p) {
    uint32_t a;
    asm("{ .reg .u64 t; cvta.to.shared.u64 t, %1; cvt.u32.u64 %0, t; }"
        : "=r"(a) : "l"(p));
    return a;
}
__device__ __forceinline__ void ldsm4(uint32_t* r, uint32_t addr) {
    asm volatile("ldmatrix.sync.aligned.m8n8.x4.shared.b16 {%0,%1,%2,%3}, [%4];"
        : "=r"(r[0]), "=r"(r[1]), "=r"(r[2]), "=r"(r[3]) : "r"(addr));
}
__device__ __forceinline__ void mmaf16(float* c, const uint32_t* a, const uint32_t* b) {
    asm volatile("mma.sync.aligned.m16n8k16.row.col.f32.f16.f16.f32 "
        "{%0,%1,%2,%3}, {%4,%5,%6,%7}, {%8,%9}, {%0,%1,%2,%3};"
        : "+f"(c[0]), "+f"(c[1]), "+f"(c[2]), "+f"(c[3])
        : "r"(a[0]), "r"(a[1]), "r"(a[2]), "r"(a[3]), "r"(b[0]), "r"(b[1]));
}
__device__ __forceinline__ void cp16(uint32_t dst, const void* src) {
    asm volatile("cp.async.cg.shared.global [%0], [%1], 16;" :: "r"(dst), "l"(src));
}
#define CP_COMMIT() asm volatile("cp.async.commit_group;" ::: "memory")
#define CP_WAIT0()  asm volatile("cp.async.wait_group 0;" ::: "memory")
__device__ __forceinline__ void bar_g(int id) {
    asm volatile("bar.sync %0, 128;" :: "r"(id) : "memory");
}
__device__ __forceinline__ float sigmoidf_(float v) { return 1.0f / (1.0f + __expf(-v)); }

// ---------------- prep kernel: x + weights -> fp16 ----------------
__global__ void prep_kernel(const float* __restrict__ x,
                            const float* rw1, const float* rw2,
                            const float* cw1, const float* cw2,
                            const float* rw3) {
    int bid = blockIdx.x, tid = threadIdx.x;
    if (bid < 18432) {
        size_t base = ((size_t)bid * 256 + tid) * 16;
        const float4* xs = (const float4*)(x + base);
        uint4* dst = (uint4*)(g_xh + base);
#pragma unroll
        for (int i = 0; i < 2; i++) {
            float4 a = xs[i * 2], b = xs[i * 2 + 1];
            __half2 h0 = __floats2half2_rn(a.x, a.y), h1 = __floats2half2_rn(a.z, a.w);
            __half2 h2 = __floats2half2_rn(b.x, b.y), h3 = __floats2half2_rn(b.z, b.w);
            uint4 v;
            v.x = *(uint32_t*)&h0; v.y = *(uint32_t*)&h1;
            v.z = *(uint32_t*)&h2; v.w = *(uint32_t*)&h3;
            dst[i] = v;
        }
    } else {
        int i = (bid - 18432) * 256 + tid;
        g_wh[0][i] = __float2half_rn(rw1[i]);
        g_wh[1][i] = __float2half_rn(rw2[i]);
        g_wh[2][i] = __float2half_rn(cw1[i]);
        g_wh[3][i] = __float2half_rn(cw2[i]);
        if (i < 128 * 256) {
            int row = i >> 8;
            g_w3h[i] = __float2half_rn((row < 68) ? rw3[i] : 0.0f);
        }
    }
}

// ---------------- load helpers ----------------
__device__ __forceinline__ void ld_W(uint32_t smb, const __half* __restrict__ w,
                                     int rows, int tid) {
    int n = rows * 32;
    for (int idx = tid; idx < n; idx += THREADS) {
        int row = idx >> 5, seg = idx & 31;
        cp16(smb + OFF_W + row * STRIDE + seg * 16, w + row * 256 + seg * 8);
    }
    CP_COMMIT();
}
// load a PAIR of tiles (128 rows) into the A region
__device__ __forceinline__ void ld_pair(uint32_t smb, const __half* __restrict__ src, int tid) {
    for (int idx = tid; idx < 4096; idx += THREADS) {
        int row = idx >> 5, seg = idx & 31;
        cp16(smb + OFF_A0 + row * STRIDE + seg * 16, src + row * 256 + seg * 8);
    }
    CP_COMMIT();
}

// ---------------- GEMMs: 16 warps, 4x4 grid over 128 rows x N outs ----------------
__device__ __forceinline__ void gemm256W(uint32_t smb, float acc[2][8][4], int tid) {
    const int lane = tid & 31, wid = tid >> 5;
    const int wm = wid >> 2, wn = wid & 3;
    const int a_row  = (lane & 7) + ((lane >> 3) & 1) * 8;
    const int a_koff = (lane >> 4) * 8;
    const int b_n    = (lane & 7) + ((lane >> 4) << 3);
    const int b_koff = ((lane >> 3) & 1) * 8;
    const uint32_t aB = smb + OFF_A0 + (uint32_t)((wm * 32 + a_row) * STRIDE + a_koff * 2);
    const uint32_t bB = smb + OFF_W + (uint32_t)((wn * 64 + b_n) * STRIDE + b_koff * 2);
#pragma unroll 4
    for (int ks = 0; ks < 16; ks++) {
        uint32_t ah0[4], ah1[4];
        ldsm4(ah0, aB + (uint32_t)(ks * 32));
        ldsm4(ah1, aB + (uint32_t)(16 * STRIDE + ks * 32));
        uint32_t bh[8][2];
#pragma unroll
        for (int p = 0; p < 4; p++) {
            uint32_t r[4];
            ldsm4(r, bB + (uint32_t)(p * 16 * STRIDE + ks * 32));
            bh[2*p][0]=r[0]; bh[2*p][1]=r[1]; bh[2*p+1][0]=r[2]; bh[2*p+1][1]=r[3];
        }
#pragma unroll
        for (int nt = 0; nt < 8; nt++) mmaf16(acc[0][nt], ah0, bh[nt]);
#pragma unroll
        for (int nt = 0; nt < 8; nt++) mmaf16(acc[1][nt], ah1, bh[nt]);
    }
}

__device__ __forceinline__ void gemm128W(uint32_t smb, float acc[2][4][4], int tid) {
    const int lane = tid & 31, wid = tid >> 5;
    const int wm = wid >> 2, wn = wid & 3;
    const int a_row  = (lane & 7) + ((lane >> 3) & 1) * 8;
    const int a_koff = (lane >> 4) * 8;
    const int b_n    = (lane & 7) + ((lane >> 4) << 3);
    const int b_koff = ((lane >> 3) & 1) * 8;
    const uint32_t aB = smb + OFF_A0 + (uint32_t)((wm * 32 + a_row) * STRIDE + a_koff * 2);
    const uint32_t bB = smb + OFF_W + (uint32_t)((wn * 32 + b_n) * STRIDE + b_koff * 2);
#pragma unroll 4
    for (int ks = 0; ks < 16; ks++) {
        uint32_t ah0[4], ah1[4];
        ldsm4(ah0, aB + (uint32_t)(ks * 32));
        ldsm4(ah1, aB + (uint32_t)(16 * STRIDE + ks * 32));
        uint32_t bh[4][2];
#pragma unroll
        for (int p = 0; p < 2; p++) {
            uint32_t r[4];
            ldsm4(r, bB + (uint32_t)(p * 16 * STRIDE + ks * 32));
            bh[2*p][0]=r[0]; bh[2*p][1]=r[1]; bh[2*p+1][0]=r[2]; bh[2*p+1][1]=r[3];
        }
#pragma unroll
        for (int nt = 0; nt < 4; nt++) mmaf16(acc[0][nt], ah0, bh[nt]);
#pragma unroll
        for (int nt = 0; nt < 4; nt++) mmaf16(acc[1][nt], ah1, bh[nt]);
    }
}

// ---------------- epilogues ----------------
// bias+relu -> fp16 in place (same row layout as reads: wm-group-local), STG pair
__device__ __forceinline__ void epi_h(char* sm, float acc[2][8][4],
                                      __half* __restrict__ dst, int tid) {
    const int lane = tid & 31, wid = tid >> 5, wm = wid >> 2, wn = wid & 3;
    const float* bias_s = (const float*)(sm + OFF_BIAS);
    bar_g(1 + wm);                       // same-wm warps (owners of these rows) done
    const int r0 = wm * 32 + (lane >> 2);
    const int c0 = wn * 64 + (lane & 3) * 2;
#pragma unroll
    for (int mt = 0; mt < 2; mt++)
#pragma unroll
    for (int nt = 0; nt < 8; nt++) {
        int col = c0 + nt * 8;
        float b0 = bias_s[col], b1 = bias_s[col + 1];
        float v0 = fmaxf(acc[mt][nt][0] + b0, 0.f);
        float v1 = fmaxf(acc[mt][nt][1] + b1, 0.f);
        float v2 = fmaxf(acc[mt][nt][2] + b0, 0.f);
        float v3 = fmaxf(acc[mt][nt][3] + b1, 0.f);
        __half2 p01 = __floats2half2_rn(v0, v1);
        __half2 p23 = __floats2half2_rn(v2, v3);
        int row = r0 + mt * 16;
        *(uint32_t*)(sm + OFF_A0 + row * STRIDE + col * 2) = *(uint32_t*)&p01;
        *(uint32_t*)(sm + OFF_A0 + (row + 8) * STRIDE + col * 2) = *(uint32_t*)&p23;
    }
    __syncthreads();
    for (int idx = tid; idx < 4096; idx += THREADS) {
        int row = idx >> 5, seg = idx & 31;
        uint4 v = *(const uint4*)(sm + OFF_A0 + row * STRIDE + seg * 16);
        *(uint4*)(dst + row * 256 + seg * 8) = v;
    }
}

// layer3 epilogue: f32 stage (different stride -> full sync first), softmax/top4
__device__ __forceinline__ void epi_softmax(char* sm, float acc3[2][4][4],
                                            int tp, int tileg0,
                                            float* __restrict__ box_out,
                                            float* __restrict__ reg_out, int tid) {
    const int lane = tid & 31, wid = tid >> 5, wm = wid >> 2, wn = wid & 3;
    const float* bias_s = (const float*)(sm + OFF_BIAS);
    float* stage = (float*)(sm + OFF_A0);      // 128 rows x 76 f32
    __syncthreads();                           // f32 stage overlaps others' fp16 rows
    const int r0 = wm * 32 + (lane >> 2);
    const int cb = (lane & 3) * 2;
#pragma unroll
    for (int mt = 0; mt < 2; mt++)
#pragma unroll
    for (int nt = 0; nt < 4; nt++) {
        int col = wn * 32 + nt * 8 + cb;
        if (col < 68) {
            int r = r0 + mt * 16;
            float b0 = bias_s[col], b1 = bias_s[col + 1];
            stage[r * 76 + col]         = acc3[mt][nt][0] + b0;
            stage[r * 76 + col + 1]     = acc3[mt][nt][1] + b1;
            stage[(r + 8) * 76 + col]   = acc3[mt][nt][2] + b0;
            stage[(r + 8) * 76 + col+1] = acc3[mt][nt][3] + b1;
        }
    }
    __syncthreads();
    {
        const int m = tid >> 2, g = tid & 3;   // 128 tokens x 4 sides = 512
        float* stat_s = (float*)(sm + OFF_STAT) + (2 * tp + (m >> 6)) * 1280 + (m & 63) * 20;
        float lg[17];
#pragma unroll
        for (int j = 0; j < 17; j++) lg[j] = stage[m * 76 + g * 17 + j];
        float mx = lg[0];
#pragma unroll
        for (int j = 1; j < 17; j++) mx = fmaxf(mx, lg[j]);
        float e[17], s = 0.f, si = 0.f;
#pragma unroll
        for (int j = 0; j < 17; j++) {
            e[j] = __expf(lg[j] - mx);
            s += e[j]; si += e[j] * (float)j;
        }
        box_out[(size_t)(tileg0 * 64 + m) * 4 + g] = si / (s * 16.0f);
        float inv = 1.0f / s, tsum = 0.f;
#pragma unroll
        for (int t4 = 0; t4 < 4; t4++) {
            float mv = -1.0f; int mi = 0;
#pragma unroll
            for (int j = 0; j < 17; j++)
                if (e[j] > mv) { mv = e[j]; mi = j; }
            float tv = mv * inv;
            stat_s[g * 5 + t4] = tv;
            tsum += tv;
            e[mi] = -1.0f;
        }
        stat_s[g * 5 + 4] = tsum * 0.25f;
    }
    float* ro = reg_out + (size_t)tileg0 * 4352;     // 128 rows x 68, contiguous
    for (int idx = tid; idx < 128 * 68; idx += THREADS) {
        int row = idx / 68;
        int col = idx - row * 68;
        ro[idx] = stage[row * 76 + col];
    }
}

// final cls epilogue: fp16 h2 in place, cls3 + quality partials concurrently
__device__ __forceinline__ void epi_cls(char* sm, float acc[2][8][4],
    int tp, int tileg0,
    const float* __restrict__ cw3, const float* __restrict__ cb3,
    const float* __restrict__ qb1, const float* __restrict__ qw2,
    const float* __restrict__ qb2, float* __restrict__ cls_out, int tid) {
    const int lane = tid & 31, wid = tid >> 5, wm = wid >> 2, wn = wid & 3;
    const float* bias_s = (const float*)(sm + OFF_BIAS);
    float* qw1_s = (float*)(sm + OFF_QW1);
    float* p1_s  = (float*)(sm + OFF_P1);
    float* p2_s  = (float*)(sm + OFF_P2);
    bar_g(1 + wm);
    const int r0 = wm * 32 + (lane >> 2);
    const int c0 = wn * 64 + (lane & 3) * 2;
#pragma unroll
    for (int mt = 0; mt < 2; mt++)
#pragma unroll
    for (int nt = 0; nt < 8; nt++) {
        int col = c0 + nt * 8;
        float b0 = bias_s[col], b1 = bias_s[col + 1];
        float v0 = fmaxf(acc[mt][nt][0] + b0, 0.f);
        float v1 = fmaxf(acc[mt][nt][1] + b1, 0.f);
        float v2 = fmaxf(acc[mt][nt][2] + b0, 0.f);
        float v3 = fmaxf(acc[mt][nt][3] + b1, 0.f);
        __half2 p01 = __floats2half2_rn(v0, v1);
        __half2 p23 = __floats2half2_rn(v2, v3);
        int row = r0 + mt * 16;
        *(uint32_t*)(sm + OFF_A0 + row * STRIDE + col * 2) = *(uint32_t*)&p01;
        *(uint32_t*)(sm + OFF_A0 + (row + 8) * STRIDE + col * 2) = *(uint32_t*)&p23;
    }
    __syncthreads();
    if (tid < 256) {
        // cls3 partials: 128 tokens x 2 K-halves
        const int m = tid & 127, half = tid >> 7;
        const char* pa = sm + OFF_A0 + m * STRIDE;
        float p = 0.0f;
        const int kb = half * 128;
        for (int k0 = kb; k0 < kb + 128; k0 += 8) {
            uint4 uh = *(const uint4*)(pa + k0 * 2);
            float4 w0 = *(const float4*)(cw3 + k0);
            float4 w1 = *(const float4*)(cw3 + k0 + 4);
            const __half2* ph = (const __half2*)&uh;
            float wv[8] = {w0.x,w0.y,w0.z,w0.w,w1.x,w1.y,w1.z,w1.w};
#pragma unroll
            for (int e2 = 0; e2 < 4; e2++) {
                float2 hv = __half22float2(ph[e2]);
                p = fmaf(hv.x, wv[e2*2],   p);
                p = fmaf(hv.y, wv[e2*2+1], p);
            }
        }
        p1_s[tid] = p;
    } else {
        // quality partials: 128 tokens x 2 O-halves (32 outputs each)
        const int t2 = tid - 256;
        const int m = t2 & 127, half = t2 >> 7;
        const float* st = (const float*)(sm + OFF_STAT) + (2 * tp + (m >> 6)) * 1280 + (m & 63) * 20;
        float qp = 0.0f;
        for (int o = half * 32; o < half * 32 + 32; o++) {
            float hsum = qb1[o];
#pragma unroll
            for (int c = 0; c < 20; c++)
                hsum = fmaf(qw1_s[o * 20 + c], st[c], hsum);
            qp = fmaf(fmaxf(hsum, 0.0f), qw2[o], qp);
        }
        p2_s[t2] = qp;
    }
    __syncthreads();
    if (tid < 128) {
        float sacc = cb3[0] + p1_s[tid] + p1_s[tid + 128];
        float q    = qb2[0] + p2_s[tid] + p2_s[tid + 128];
        cls_out[tileg0 * 64 + tid] = sigmoidf_(sacc) * sigmoidf_(q);
    }
}

// ---------------- phase driver ----------------
// MODE: 0 = hidden layer, 1 = reg layer3, 2 = cls final
// Entry condition: W for this phase + pair(0,1) already issued via cp.async.
template<int MODE>
__device__ __forceinline__ void run_phase(char* sm, uint32_t smb, int tid, int tile0,
    const __half* __restrict__ src, __half* __restrict__ dst,
    const float* __restrict__ bias,
    const __half* __restrict__ nextW, int nextWrows,
    const __half* __restrict__ nextsrc,
    const float* cw3, const float* cb3,
    const float* qb1, const float* qw2, const float* qb2,
    float* box_out, float* reg_out, float* cls_out) {
    float* bias_s = (float*)(sm + OFF_BIAS);
    for (int tp = 0; tp < 2; tp++) {
        if (tp == 0) {
            if (MODE == 1) {
                if (tid < 128) bias_s[tid] = (tid < 68) ? bias[tid] : 0.0f;
            } else {
                if (tid < 256) bias_s[tid] = bias[tid];
            }
        }
        CP_WAIT0();
        __syncthreads();                 // W + pair ready; bias visible
        if (MODE == 1) {
            float a3[2][4][4];
#pragma unroll
            for (int i = 0; i < 32; i++) ((float*)a3)[i] = 0.f;
            gemm128W(smb, a3, tid);
            epi_softmax(sm, a3, tp, tile0 + 2 * tp, box_out, reg_out, tid);
        } else {
            float a[2][8][4];
#pragma unroll
            for (int i = 0; i < 64; i++) ((float*)a)[i] = 0.f;
            gemm256W(smb, a, tid);
            if (MODE == 0)
                epi_h(sm, a, dst + (size_t)(tile0 + 2 * tp) * 16384, tid);
            else
                epi_cls(sm, a, tp, tile0 + 2 * tp, cw3, cb3, qb1, qw2, qb2, cls_out, tid);
        }
        __syncthreads();                 // all buffer reads retired
        if (tp == 0)
            ld_pair(smb, src + (size_t)2 * 16384, tid);
    }
    // safe: post-epilogue __syncthreads ordered after all W reads
    if (nextW) ld_W(smb, nextW, nextWrows, tid);
    if (nextsrc) {
        __threadfence();                 // our scratch STGs visible to cp.async
        ld_pair(smb, nextsrc + (size_t)tile0 * 16384, tid);
    }
}

// ---------------- main kernel ----------------
__global__ void __launch_bounds__(THREADS, 1) gfocal_ws_kernel(
    const float* __restrict__ cb1, const float* __restrict__ cb2,
    const float* __restrict__ cw3, const float* __restrict__ cb3,
    const float* __restrict__ rb1, const float* __restrict__ rb2,
    const float* __restrict__ rb3,
    const float* __restrict__ qw1, const float* __restrict__ qb1,
    const float* __restrict__ qw2, const float* __restrict__ qb2,
    float* __restrict__ cls_out, float* __restrict__ box_out,
    float* __restrict__ reg_out) {
    extern __shared__ char sm[];
    const uint32_t smb = smem_u32(sm);
    const int tid = threadIdx.x;
    const int tile0 = blockIdx.x * TPC;

    float* qw1_s = (float*)(sm + OFF_QW1);
    for (int idx = tid; idx < 1280; idx += THREADS) qw1_s[idx] = qw1[idx];

    // prologue: W of phase 1 + first pair
    ld_W(smb, g_wh[0], 256, tid);
    ld_pair(smb, g_xh + (size_t)tile0 * 16384, tid);

    // phase 1: reg layer1   x -> h1
    run_phase<0>(sm, smb, tid, tile0, g_xh + (size_t)tile0 * 16384, g_h1,
                 rb1, g_wh[1], 256, g_h1,
                 cw3, cb3, qb1, qw2, qb2, box_out, reg_out, cls_out);
    // phase 2: reg layer2   h1 -> h2
    run_phase<0>(sm, smb, tid, tile0, g_h1 + (size_t)tile0 * 16384, g_h2,
                 rb2, g_w3h, 128, g_h2,
                 cw3, cb3, qb1, qw2, qb2, box_out, reg_out, cls_out);
    // phase 3: reg layer3   h2 -> softmax/top4/box/reg_pred
    run_phase<1>(sm, smb, tid, tile0, g_h2 + (size_t)tile0 * 16384, (/*unused*/ __half*)g_h1,
                 rb3, g_wh[2], 256, g_xh,
                 cw3, cb3, qb1, qw2, qb2, box_out, reg_out, cls_out);
    // phase 4: cls layer1   x -> h1
    run_phase<0>(sm, smb, tid, tile0, g_xh + (size_t)tile0 * 16384, g_h1,
                 cb1, g_wh[3], 256, g_h1,
                 cw3, cb3, qb1, qw2, qb2, box_out, reg_out, cls_out);
    // phase 5: cls layer2 + cls3 + quality -> cls_out
    run_phase<2>(sm, smb, tid, tile0, g_h1 + (size_t)tile0 * 16384, (/*unused*/ __half*)g_h2,
                 cb2, (const __half*)0, 0, (const __half*)0,
                 cw3, cb3, qb1, qw2, qb2, box_out, reg_out, cls_out);
}

extern "C" void kernel_launch(void* const* d_in, const int* in_sizes, int n_in,
                              void* d_out, int out_size) {
    const float* x   = (const float*)d_in[0];
    const float* cw1 = (const float*)d_in[1];
    const float* cb1 = (const float*)d_in[2];
    const float* cw2 = (const float*)d_in[3];
    const float* cb2 = (const float*)d_in[4];
    const float* cw3 = (const float*)d_in[5];
    const float* cb3 = (const float*)d_in[6];
    const float* rw1 = (const float*)d_in[7];
    const float* rb1 = (const float*)d_in[8];
    const float* rw2 = (const float*)d_in[9];
    const float* rb2 = (const float*)d_in[10];
    const float* rw3 = (const float*)d_in[11];
    const float* rb3 = (const float*)d_in[12];
    const float* qw1 = (const float*)d_in[13];
    const float* qb1 = (const float*)d_in[14];
    const float* qw2 = (const float*)d_in[15];
    const float* qb2 = (const float*)d_in[16];

    float* out = (float*)d_out;
    float* cls_out = out;
    float* box_out = out + NTOK;
    float* reg_out = out + NTOK + (size_t)NTOK * 4;

    prep_kernel<<<18688, 256>>>(x, rw1, rw2, cw1, cw2, rw3);

    cudaFuncSetAttribute(gfocal_ws_kernel,
                         cudaFuncAttributeMaxDynamicSharedMemorySize, SMEM_BYTES);
    gfocal_ws_kernel<<<NCTA, THREADS, SMEM_BYTES>>>(
        cb1, cb2, cw3, cb3, rb1, rb2, rb3,
        qw1, qb1, qw2, qb2,
        cls_out, box_out, reg_out);
}